// round 10
// baseline (speedup 1.0000x reference)
#include <cuda_runtime.h>
#include <cuda_bf16.h>
#include <cstdint>

// ---------------- problem constants ----------------
#define BB    2
#define CFEAT 128
#define HH    64
#define WW    128
#define GG    16
#define CPG   8
#define DDISP 48
#define HID   32
#define NEG   0.2f
#define EPSBN 1e-5f

#define SPA    (DDISP*HH*WW)
#define X_ELEMS (BB*HID*SPA)
#define NROWS  (BB*DDISP*HH)          // 6144
#define PKE    (BB*16*SPA)

// ---------------- scratch ----------------
__device__ float    g_buf0[X_ELEMS];
__device__ uint32_t g_ph[2*PKE];
__device__ uint32_t g_pl[2*PKE];
__device__ float    g_rsum[HID*NROWS];
__device__ float    g_rsq [HID*NROWS];
__device__ float2   g_ss  [HID];
// packed weight fragments: [tap 27][chunk NCH][half 2][j 8][n' 32] (n' = (n&7)*4 + (n>>3))
#define WP_LAYER_U32 (27*2*2*8*32)
__device__ uint32_t g_wp[4*WP_LAYER_U32];

// ---------------- mma / ldmatrix helpers ----------------
__device__ __forceinline__ void mma16816(float d[4], const uint32_t a[4],
                                         uint32_t b0, uint32_t b1)
{
    asm volatile(
        "mma.sync.aligned.m16n8k16.row.col.f32.bf16.bf16.f32 "
        "{%0,%1,%2,%3}, {%4,%5,%6,%7}, {%8,%9}, {%0,%1,%2,%3};\n"
        : "+f"(d[0]), "+f"(d[1]), "+f"(d[2]), "+f"(d[3])
        : "r"(a[0]), "r"(a[1]), "r"(a[2]), "r"(a[3]), "r"(b0), "r"(b1));
}
__device__ __forceinline__ void ldmx4(uint32_t r[4], uint32_t addr)
{
    asm volatile("ldmatrix.sync.aligned.m8n8.x4.shared.b16 {%0,%1,%2,%3}, [%4];"
                 : "=r"(r[0]), "=r"(r[1]), "=r"(r[2]), "=r"(r[3]) : "r"(addr));
}
__device__ __forceinline__ uint32_t pack_bf16x2(__nv_bfloat16 lo, __nv_bfloat16 hi)
{
    unsigned short u0 = *reinterpret_cast<unsigned short*>(&lo);
    unsigned short u1 = *reinterpret_cast<unsigned short*>(&hi);
    return (uint32_t)u0 | ((uint32_t)u1 << 16);
}
__device__ __forceinline__ void split_pack(float v0, float v1,
                                           uint32_t& hi, uint32_t& lo)
{
    __nv_bfloat16 h0 = __float2bfloat16_rn(v0);
    __nv_bfloat16 h1 = __float2bfloat16_rn(v1);
    __nv_bfloat16 l0 = __float2bfloat16_rn(v0 - __bfloat162float(h0));
    __nv_bfloat16 l1 = __float2bfloat16_rn(v1 - __bfloat162float(h1));
    hi = pack_bf16x2(h0, h1);
    lo = pack_bf16x2(l0, l1);
}

// ---------------- volume build (packed hi/lo) ----------------
__global__ void vol_pack_kernel(const float* __restrict__ left,
                                const float* __restrict__ right,
                                uint32_t* __restrict__ ph,
                                uint32_t* __restrict__ pl)
{
    int h = blockIdx.x % HH;
    int p = (blockIdx.x / HH) % 8;
    int b = blockIdx.x / (HH*8);
    int w = threadIdx.x;

    __shared__ float sR[16][WW];
    float l[16];
    const float* lp = left  + (((size_t)b*CFEAT + p*16)*HH + h)*WW + w;
    const float* rp = right + (((size_t)b*CFEAT + p*16)*HH + h)*WW + w;
#pragma unroll
    for (int c = 0; c < 16; c++) {
        l[c]     = lp[(size_t)c*HH*WW];
        sR[c][w] = rp[(size_t)c*HH*WW];
    }
    __syncthreads();

    uint32_t* hp  = ph + ((size_t)(b*8 + p)*DDISP)*(HH*WW) + h*WW + w;
    uint32_t* lp2 = pl + ((size_t)(b*8 + p)*DDISP)*(HH*WW) + h*WW + w;
    for (int d = 0; d < DDISP; d++) {
        float s0 = 0.f, s1 = 0.f;
        if (w >= d) {
            int ws = w - d;
#pragma unroll
            for (int c = 0; c < 8; c++)  s0 += l[c]*sR[c][ws];
#pragma unroll
            for (int c = 8; c < 16; c++) s1 += l[c]*sR[c][ws];
        }
        s0 *= (1.0f/CPG); s1 *= (1.0f/CPG);
        uint32_t hi, lo;
        split_pack(s0, s1, hi, lo);
        hp [(size_t)d*HH*WW] = hi;
        lp2[(size_t)d*HH*WW] = lo;
    }
}

// ---------------- weight fragment pre-pack (n-permuted for LDS.128) ----------------
__global__ void wpack_kernel(const float* __restrict__ wg, int cin,
                             uint32_t* __restrict__ dst)
{
    const int t = blockIdx.x;
    const int nch = cin / 16;
    const int elems = nch * 512;
    for (int i = threadIdx.x; i < elems; i += 256) {
        int n  = i & 31;
        int j  = (i >> 5) & 7;
        int hf = (i >> 8) & 1;
        int c  = i >> 9;
        int ci0 = c*16 + 2*j;
        float w0 = wg[((size_t)n*cin + ci0    )*27 + t];
        float w1 = wg[((size_t)n*cin + ci0 + 1)*27 + t];
        __nv_bfloat16 p0, p1;
        if (hf == 0) {
            p0 = __float2bfloat16_rn(w0);
            p1 = __float2bfloat16_rn(w1);
        } else {
            __nv_bfloat16 h0 = __float2bfloat16_rn(w0);
            __nv_bfloat16 h1 = __float2bfloat16_rn(w1);
            p0 = __float2bfloat16_rn(w0 - __bfloat162float(h0));
            p1 = __float2bfloat16_rn(w1 - __bfloat162float(h1));
        }
        int nprime = (n & 7)*4 + (n >> 3);
        dst[((((size_t)t*nch + c)*2 + hf)*8 + j)*32 + nprime] = pack_bf16x2(p0, p1);
    }
}

// ---------------- BN split pass ----------------
__global__ __launch_bounds__(256)
void split_kernel(const float* __restrict__ y,
                  uint32_t* __restrict__ ph, uint32_t* __restrict__ pl)
{
    int idx = blockIdx.x * 256 + threadIdx.x;
    int r = idx % SPA;
    int p = (idx / SPA) % 16;
    int b = idx / (16*SPA);

    float v0 = y[((size_t)b*HID + 2*p    )*SPA + r];
    float v1 = y[((size_t)b*HID + 2*p + 1)*SPA + r];
    float2 s0 = g_ss[2*p], s1 = g_ss[2*p + 1];
    v0 = fmaf(s0.x, v0, s0.y); v0 = (v0 > 0.f) ? v0 : NEG*v0;
    v1 = fmaf(s1.x, v1, s1.y); v1 = (v1 > 0.f) ? v1 : NEG*v1;
    uint32_t hi, lo;
    split_pack(v0, v1, hi, lo);
    ph[idx] = hi;
    pl[idx] = lo;
}

// ---------------- pipelined implicit-GEMM conv3d (ldmatrix + LDS.128 B) ----------------
#define SD_STRIDE 132

template<int CIN>
__global__ __launch_bounds__(256)
void conv_mma(const uint32_t* __restrict__ ph,
              const uint32_t* __restrict__ pl,
              const uint32_t* __restrict__ wp,
              float* __restrict__ out)
{
    constexpr int NCH   = CIN / 16;
    constexpr int NPAIR = CIN / 2;
    constexpr int RS32  = (CIN == 32) ? 20 : 12;   // u32 stride per w-row (conflict-free ldmatrix)
    constexpr int RSHW  = RS32 * 2;
    constexpr int SWBUF = 3*NCH*2*8*40;            // u32 per B buffer
    constexpr int ABUF  = 130*RS32;                // u32 per A buffer (one of hi/lo)
    constexpr int NAIT  = (NPAIR*32)/256;          // A uint4 loads per thread (2 or 1)
    constexpr int NW4   = NCH*384;                 // B uint4 count per tap-group
    constexpr int NWIT  = (NW4 + 255)/256;         // 3 or 2

    extern __shared__ __align__(16) uint8_t smem[];
    uint32_t* sb   = (uint32_t*)smem;
    float*    sD   = (float*)smem;
    float*    sSum = sD + HID*SD_STRIDE;
    float*    sSq  = sSum + 256;

    const int row = blockIdx.x;
    const int b = row / (DDISP*HH);
    const int d = (row / HH) % DDISP;
    const int h = row % HH;

    const int tid  = threadIdx.x;
    const int warp = tid >> 5;
    const int lane = tid & 31;
    const int g    = lane >> 2;
    const int p4   = lane & 3;
    const int m_base = warp * 16;
    const int HW = HH*WW;

    // ldmatrix lane addressing: matrices 0..3 = (m0-7,k0-7),(m8-15,k0-7),(m0-7,k8-15),(m8-15,k8-15)
    const int mi = (lane >> 3) & 1;
    const int ki = lane >> 4;
    const int rr = lane & 7;
    const uint32_t aoff_hw = (uint32_t)((m_base + mi*8 + rr)*RSHW + ki*8);

    const uint32_t smem_u = (uint32_t)__cvta_generic_to_shared(smem);
    const uint32_t sAh_b  = smem_u + 2*SWBUF*4;
    const uint32_t sAl_b  = sAh_b + 2*ABUF*4;

    float acc[4][4];
#pragma unroll
    for (int nb = 0; nb < 4; nb++)
#pragma unroll
        for (int v = 0; v < 4; v++) acc[nb][v] = 0.f;

    // zero pad rows (w=-1 -> row0, w=128 -> row129) in both buffers, both arrays
    if (tid < 2*2*2*NPAIR) {
        int e = tid;
        int buf = e & 1, arr = (e >> 1) & 1, rsel = (e >> 2) & 1, p = e >> 3;
        sb[2*SWBUF + arr*2*ABUF + buf*ABUF + (rsel ? 129 : 0)*RS32 + p] = 0;
    }

    // valid tap list
    int tdd[9], thh[9], ttk[9]; int tcnt = 0;
    for (int kd = 0; kd < 3; kd++) {
        int dd = d + kd - 1; if (dd < 0 || dd >= DDISP) continue;
        for (int kh = 0; kh < 3; kh++) {
            int h2 = h + kh - 1; if (h2 < 0 || h2 >= HH) continue;
            tdd[tcnt] = dd; thh[tcnt] = h2; ttk[tcnt] = (kd*3 + kh)*3; tcnt++;
        }
    }

    uint4 pvh[NAIT], pvl[NAIT], pw[NWIT];

    auto LDG = [&](int t) {
        const int dd = tdd[t], h2 = thh[t];
#pragma unroll
        for (int k = 0; k < NAIT; k++) {
            int e = tid + k*256;
            int p  = e & (NPAIR - 1);
            int wg = e / NPAIR;                    // 0..31
            size_t src = ((size_t)(b*NPAIR + p)*DDISP + dd)*HW + h2*WW + wg*4;
            pvh[k] = *(const uint4*)&ph[src];
            pvl[k] = *(const uint4*)&pl[src];
        }
        const uint4* s4 = (const uint4*)(wp + (size_t)ttk[t]*(NCH*2*8*32));
#pragma unroll
        for (int k = 0; k < NWIT; k++) {
            int idx = tid + k*256;
            if (idx < NW4) pw[k] = s4[idx];
        }
    };
    auto STS = [&](int buf) {
#pragma unroll
        for (int k = 0; k < NAIT; k++) {
            int e = tid + k*256;
            int p  = e & (NPAIR - 1);
            int wg = e / NPAIR;
            uint32_t* dh = sb + 2*SWBUF + buf*ABUF + (wg*4 + 1)*RS32 + p;
            uint32_t* dl = dh + 2*ABUF;
            dh[0*RS32] = pvh[k].x; dh[1*RS32] = pvh[k].y;
            dh[2*RS32] = pvh[k].z; dh[3*RS32] = pvh[k].w;
            dl[0*RS32] = pvl[k].x; dl[1*RS32] = pvl[k].y;
            dl[2*RS32] = pvl[k].z; dl[3*RS32] = pvl[k].w;
        }
#pragma unroll
        for (int k = 0; k < NWIT; k++) {
            int idx = tid + k*256;
            if (idx < NW4) {
                int G = idx*4;
                int r = G >> 5, cpos = G & 31;
                *(uint4*)(sb + buf*SWBUF + r*40 + cpos) = pw[k];
            }
        }
    };
    auto COMPUTE = [&](int buf) {
        const uint32_t ah_base = sAh_b + (uint32_t)buf*ABUF*4;
        const uint32_t al_base = sAl_b + (uint32_t)buf*ABUF*4;
        const uint32_t* wv = sb + buf*SWBUF;
#pragma unroll
        for (int kw = 0; kw < 3; kw++) {
#pragma unroll
            for (int c = 0; c < NCH; c++) {
                const uint32_t off = (aoff_hw + (uint32_t)(kw*RSHW + c*16)) * 2;
                uint32_t ah[4], al[4];
                ldmx4(ah, ah_base + off);
                ldmx4(al, al_base + off);
                const uint32_t* wb = wv + ((kw*NCH + c)*2)*8*40;
                uint4 bh0 = *(const uint4*)(wb + p4*40 + g*4);
                uint4 bh1 = *(const uint4*)(wb + (p4 + 4)*40 + g*4);
                uint4 bl0 = *(const uint4*)(wb + 320 + p4*40 + g*4);
                uint4 bl1 = *(const uint4*)(wb + 320 + (p4 + 4)*40 + g*4);
                mma16816(acc[0], ah, bh0.x, bh1.x);
                mma16816(acc[0], ah, bl0.x, bl1.x);
                mma16816(acc[0], al, bh0.x, bh1.x);
                mma16816(acc[1], ah, bh0.y, bh1.y);
                mma16816(acc[1], ah, bl0.y, bl1.y);
                mma16816(acc[1], al, bh0.y, bh1.y);
                mma16816(acc[2], ah, bh0.z, bh1.z);
                mma16816(acc[2], ah, bl0.z, bl1.z);
                mma16816(acc[2], al, bh0.z, bh1.z);
                mma16816(acc[3], ah, bh0.w, bh1.w);
                mma16816(acc[3], ah, bl0.w, bl1.w);
                mma16816(acc[3], al, bh0.w, bh1.w);
            }
        }
    };

    // software pipeline over taps
    LDG(0);
    STS(0);
    __syncthreads();
#pragma unroll 1
    for (int t = 0; t < tcnt; t++) {
        if (t + 1 < tcnt) LDG(t + 1);
        COMPUTE(t & 1);
        if (t + 1 < tcnt) {
            STS((t + 1) & 1);
            __syncthreads();
        }
    }

    // ---- epilogue: smem transpose -> coalesced stores + fused BN partial sums
    __syncthreads();
#pragma unroll
    for (int nb = 0; nb < 4; nb++) {
        const int co = nb*8 + 2*p4;
        sD[(co    )*SD_STRIDE + m_base + g    ] = acc[nb][0];
        sD[(co + 1)*SD_STRIDE + m_base + g    ] = acc[nb][1];
        sD[(co    )*SD_STRIDE + m_base + g + 8] = acc[nb][2];
        sD[(co + 1)*SD_STRIDE + m_base + g + 8] = acc[nb][3];
    }
    __syncthreads();
    for (int i = tid; i < HID*32; i += 256) {
        const int co = i >> 5;
        const int q  = (i & 31) * 4;
        float4 v = *(const float4*)&sD[co*SD_STRIDE + q];
        *(float4*)&out[(((size_t)b*HID + co)*DDISP + d)*(HH*WW) + h*WW + q] = v;
    }
    {
        const int co = tid >> 3;
        const int sg = tid & 7;
        const float* rp = &sD[co*SD_STRIDE + sg*16];
        float s = 0.f, sq = 0.f;
#pragma unroll
        for (int j = 0; j < 16; j++) { float v = rp[j]; s += v; sq += v*v; }
        sSum[co*8 + sg] = s;
        sSq [co*8 + sg] = sq;
    }
    __syncthreads();
    if (tid < HID) {
        float S = 0.f, Q = 0.f;
#pragma unroll
        for (int k = 0; k < 8; k++) { S += sSum[tid*8 + k]; Q += sSq[tid*8 + k]; }
        g_rsum[(size_t)tid*NROWS + row] = S;
        g_rsq [(size_t)tid*NROWS + row] = Q;
    }
}

// ---------------- BN finalize ----------------
__global__ __launch_bounds__(256)
void finalize2_kernel(const float* __restrict__ gamma,
                      const float* __restrict__ beta)
{
    const int ch = blockIdx.x;
    float s = 0.f, sq = 0.f;
    for (int r = threadIdx.x; r < NROWS; r += 256) {
        s  += g_rsum[(size_t)ch*NROWS + r];
        sq += g_rsq [(size_t)ch*NROWS + r];
    }
    __shared__ float rs[256], rq[256];
    rs[threadIdx.x] = s; rq[threadIdx.x] = sq;
    __syncthreads();
    for (int st = 128; st > 0; st >>= 1) {
        if (threadIdx.x < st) {
            rs[threadIdx.x] += rs[threadIdx.x + st];
            rq[threadIdx.x] += rq[threadIdx.x + st];
        }
        __syncthreads();
    }
    if (threadIdx.x == 0) {
        const float N = (float)(BB*SPA);
        float mean = rs[0] / N;
        float var  = fmaxf(rq[0] / N - mean*mean, 0.f);
        float scale = gamma[ch] * rsqrtf(var + EPSBN);
        g_ss[ch] = make_float2(scale, beta[ch] - mean*scale);
    }
}

// ---------------- final conv (32 -> 1), smem-tiled scalar ----------------
#define TD 2
#define TH 8
#define TW 16
#define CD 4
#define CH 10
#define CWD 18
#define CWP 19
#define CHUNK 4

__global__ __launch_bounds__(256)
void final_kernel(const float* __restrict__ x,
                  const float* __restrict__ wf,
                  const float* __restrict__ bf,
                  float* __restrict__ out)
{
    __shared__ float sIn[CHUNK][CD][CH][CWP];
    __shared__ float sw[HID*27];
    __shared__ float2 sss[HID];

    const int w0 = blockIdx.x * TW;
    const int h0 = blockIdx.y * TH;
    const int bz = blockIdx.z;
    const int b  = bz / (DDISP/TD);
    const int d0 = (bz % (DDISP/TD)) * TD;
    const int tid = threadIdx.x;

    const int tdz = tid >> 7;
    const int thy = (tid >> 4) & 7;
    const int twx = tid & 15;

    for (int i = tid; i < HID*27; i += 256) sw[i] = wf[i];
    if (tid < HID) sss[tid] = g_ss[tid];
    __syncthreads();

    float acc = 0.f;
    for (int c0 = 0; c0 < HID; c0 += CHUNK) {
        __syncthreads();
        for (int i = tid; i < CHUNK*CD*CH*CWD; i += 256) {
            int c  = i / (CD*CH*CWD);
            int r  = i % (CD*CH*CWD);
            int dz = r / (CH*CWD);
            int r2 = r % (CH*CWD);
            int hy = r2 / CWD;
            int wx = r2 % CWD;
            int gd = d0 - 1 + dz;
            int gh = h0 - 1 + hy;
            int gw = w0 - 1 + wx;
            float val = 0.f;
            if (gd >= 0 && gd < DDISP && gh >= 0 && gh < HH && gw >= 0 && gw < WW) {
                val = x[(((size_t)b*HID + (c0 + c))*DDISP + gd)*(HH*WW) + gh*WW + gw];
                float2 s = sss[c0 + c];
                val = fmaf(s.x, val, s.y);
                val = (val > 0.f) ? val : NEG*val;
            }
            sIn[c][dz][hy][wx] = val;
        }
        __syncthreads();

#pragma unroll 1
        for (int c = 0; c < CHUNK; c++) {
#pragma unroll
            for (int kd = 0; kd < 3; kd++) {
#pragma unroll
                for (int kh = 0; kh < 3; kh++) {
#pragma unroll
                    for (int kw = 0; kw < 3; kw++) {
                        acc = fmaf(sw[(c0 + c)*27 + (kd*3 + kh)*3 + kw],
                                   sIn[c][tdz + kd][thy + kh][twx + kw], acc);
                    }
                }
            }
        }
    }

    const int gd = d0 + tdz, gh = h0 + thy, gw = w0 + twx;
    out[(((size_t)b*DDISP + gd)*HH + gh)*WW + gw] = acc + bf[0];
}

// ---------------- launch ----------------
extern "C" void kernel_launch(void* const* d_in, const int* in_sizes, int n_in,
                              void* d_out, int out_size)
{
    const float* left  = (const float*)d_in[0];
    const float* right = (const float*)d_in[1];
    const float* w1 = (const float*)d_in[2];
    const float* g1 = (const float*)d_in[3];
    const float* b1 = (const float*)d_in[4];
    const float* w2 = (const float*)d_in[5];
    const float* g2 = (const float*)d_in[6];
    const float* b2 = (const float*)d_in[7];
    const float* w3 = (const float*)d_in[8];
    const float* g3 = (const float*)d_in[9];
    const float* b3 = (const float*)d_in[10];
    const float* w4 = (const float*)d_in[11];
    const float* g4 = (const float*)d_in[12];
    const float* b4 = (const float*)d_in[13];
    const float* wf = (const float*)d_in[14];
    const float* bf = (const float*)d_in[15];
    float* out = (float*)d_out;
    (void)in_sizes; (void)n_in; (void)out_size;

    float *buf;
    uint32_t *wp, *phb, *plb;
    cudaGetSymbolAddress((void**)&buf, g_buf0);
    cudaGetSymbolAddress((void**)&wp,  g_wp);
    cudaGetSymbolAddress((void**)&phb, g_ph);
    cudaGetSymbolAddress((void**)&plb, g_pl);
    uint32_t* ph0 = phb;        uint32_t* pl0 = plb;
    uint32_t* ph1 = phb + PKE;  uint32_t* pl1 = plb + PKE;

    // dynamic smem sizes (bytes)
    const int SD_BYTES = (HID*SD_STRIDE + 512)*4;
    const int SM16_raw = (2*(3*1*2*8*40) + 4*(130*12))*4;   // 40320
    const int SM32_raw = (2*(3*2*2*8*40) + 4*(130*20))*4;   // 72320
    const int SMEM16 = (SM16_raw > SD_BYTES) ? SM16_raw : SD_BYTES;
    const int SMEM32 = (SM32_raw > SD_BYTES) ? SM32_raw : SD_BYTES;

    cudaFuncSetAttribute(conv_mma<16>, cudaFuncAttributeMaxDynamicSharedMemorySize, SMEM16);
    cudaFuncSetAttribute(conv_mma<32>, cudaFuncAttributeMaxDynamicSharedMemorySize, SMEM32);

    dim3 cgrid(WW/TW, HH/TH, BB*(DDISP/TD));
    const int SPLIT_GRID = PKE/256;

    wpack_kernel<<<27, 256>>>(w1, 16, wp + 0*WP_LAYER_U32);
    wpack_kernel<<<27, 256>>>(w2, 32, wp + 1*WP_LAYER_U32);
    wpack_kernel<<<27, 256>>>(w3, 32, wp + 2*WP_LAYER_U32);
    wpack_kernel<<<27, 256>>>(w4, 32, wp + 3*WP_LAYER_U32);

    vol_pack_kernel<<<BB*8*HH, 128>>>(left, right, ph0, pl0);

    conv_mma<16><<<NROWS, 256, SMEM16>>>(ph0, pl0, wp + 0*WP_LAYER_U32, buf);
    finalize2_kernel<<<HID, 256>>>(g1, b1);
    split_kernel<<<SPLIT_GRID, 256>>>(buf, ph1, pl1);

    conv_mma<32><<<NROWS, 256, SMEM32>>>(ph1, pl1, wp + 1*WP_LAYER_U32, buf);
    finalize2_kernel<<<HID, 256>>>(g2, b2);
    split_kernel<<<SPLIT_GRID, 256>>>(buf, ph0, pl0);

    conv_mma<32><<<NROWS, 256, SMEM32>>>(ph0, pl0, wp + 2*WP_LAYER_U32, buf);
    finalize2_kernel<<<HID, 256>>>(g3, b3);
    split_kernel<<<SPLIT_GRID, 256>>>(buf, ph1, pl1);

    conv_mma<32><<<NROWS, 256, SMEM32>>>(ph1, pl1, wp + 3*WP_LAYER_U32, buf);
    finalize2_kernel<<<HID, 256>>>(g4, b4);

    final_kernel<<<cgrid, 256>>>(buf, wf, bf, out);
}

// round 13
// speedup vs baseline: 1.1964x; 1.1964x over previous
#include <cuda_runtime.h>
#include <cuda_bf16.h>
#include <cstdint>

// ---------------- problem constants ----------------
#define BB    2
#define CFEAT 128
#define HH    64
#define WW    128
#define GG    16
#define CPG   8
#define DDISP 48
#define HID   32
#define NEG   0.2f
#define EPSBN 1e-5f

#define SPA    (DDISP*HH*WW)
#define X_ELEMS (BB*HID*SPA)
#define NROWS  (BB*DDISP*HH)          // 6144
#define PKE    (BB*16*SPA)

// ---------------- scratch ----------------
__device__ float    g_buf0[X_ELEMS];
__device__ uint32_t g_ph[2*PKE];
__device__ uint32_t g_pl[2*PKE];
__device__ float    g_rsum[HID*NROWS];
__device__ float    g_rsq [HID*NROWS];
__device__ float2   g_ss  [HID];
// packed weight fragments: [tap 27][chunk NCH][half 2][j 8][n' 32], n' = (n&7)*4 + (n>>3)
#define WP_LAYER_U32 (27*2*2*8*32)
__device__ uint32_t g_wp[4*WP_LAYER_U32];

// ---------------- mma.sync m16n8k16 bf16 ----------------
__device__ __forceinline__ void mma16816(float d[4], const uint32_t a[4],
                                         uint32_t b0, uint32_t b1)
{
    asm volatile(
        "mma.sync.aligned.m16n8k16.row.col.f32.bf16.bf16.f32 "
        "{%0,%1,%2,%3}, {%4,%5,%6,%7}, {%8,%9}, {%0,%1,%2,%3};\n"
        : "+f"(d[0]), "+f"(d[1]), "+f"(d[2]), "+f"(d[3])
        : "r"(a[0]), "r"(a[1]), "r"(a[2]), "r"(a[3]), "r"(b0), "r"(b1));
}

__device__ __forceinline__ uint32_t pack_bf16x2(__nv_bfloat16 lo, __nv_bfloat16 hi)
{
    unsigned short u0 = *reinterpret_cast<unsigned short*>(&lo);
    unsigned short u1 = *reinterpret_cast<unsigned short*>(&hi);
    return (uint32_t)u0 | ((uint32_t)u1 << 16);
}

__device__ __forceinline__ void split_pack(float v0, float v1,
                                           uint32_t& hi, uint32_t& lo)
{
    __nv_bfloat16 h0 = __float2bfloat16_rn(v0);
    __nv_bfloat16 h1 = __float2bfloat16_rn(v1);
    __nv_bfloat16 l0 = __float2bfloat16_rn(v0 - __bfloat162float(h0));
    __nv_bfloat16 l1 = __float2bfloat16_rn(v1 - __bfloat162float(h1));
    hi = pack_bf16x2(h0, h1);
    lo = pack_bf16x2(l0, l1);
}

// ---------------- volume build, emitting packed hi/lo directly ----------------
__global__ void vol_pack_kernel(const float* __restrict__ left,
                                const float* __restrict__ right,
                                uint32_t* __restrict__ ph,
                                uint32_t* __restrict__ pl)
{
    int h = blockIdx.x % HH;
    int p = (blockIdx.x / HH) % 8;
    int b = blockIdx.x / (HH*8);
    int w = threadIdx.x;                       // 128

    __shared__ float sR[16][WW];
    float l[16];
    const float* lp = left  + (((size_t)b*CFEAT + p*16)*HH + h)*WW + w;
    const float* rp = right + (((size_t)b*CFEAT + p*16)*HH + h)*WW + w;
#pragma unroll
    for (int c = 0; c < 16; c++) {
        l[c]     = lp[(size_t)c*HH*WW];
        sR[c][w] = rp[(size_t)c*HH*WW];
    }
    __syncthreads();

    uint32_t* hp  = ph + ((size_t)(b*8 + p)*DDISP)*(HH*WW) + h*WW + w;
    uint32_t* lp2 = pl + ((size_t)(b*8 + p)*DDISP)*(HH*WW) + h*WW + w;
    for (int d = 0; d < DDISP; d++) {
        float s0 = 0.f, s1 = 0.f;
        if (w >= d) {
            int ws = w - d;
#pragma unroll
            for (int c = 0; c < 8; c++)  s0 += l[c]*sR[c][ws];
#pragma unroll
            for (int c = 8; c < 16; c++) s1 += l[c]*sR[c][ws];
        }
        s0 *= (1.0f/CPG); s1 *= (1.0f/CPG);
        uint32_t hi, lo;
        split_pack(s0, s1, hi, lo);
        hp [(size_t)d*HH*WW] = hi;
        lp2[(size_t)d*HH*WW] = lo;
    }
}

// ---------------- weight fragment pre-pack (n-permuted for LDS.128) ----------------
__global__ void wpack_kernel(const float* __restrict__ wg, int cin,
                             uint32_t* __restrict__ dst)
{
    const int t = blockIdx.x;            // 0..26
    const int nch = cin / 16;
    const int elems = nch * 512;
    for (int i = threadIdx.x; i < elems; i += 256) {
        int n  = i & 31;
        int j  = (i >> 5) & 7;
        int hf = (i >> 8) & 1;
        int c  = i >> 9;
        int ci0 = c*16 + 2*j;
        float w0 = wg[((size_t)n*cin + ci0    )*27 + t];
        float w1 = wg[((size_t)n*cin + ci0 + 1)*27 + t];
        __nv_bfloat16 p0, p1;
        if (hf == 0) {
            p0 = __float2bfloat16_rn(w0);
            p1 = __float2bfloat16_rn(w1);
        } else {
            __nv_bfloat16 h0 = __float2bfloat16_rn(w0);
            __nv_bfloat16 h1 = __float2bfloat16_rn(w1);
            p0 = __float2bfloat16_rn(w0 - __bfloat162float(h0));
            p1 = __float2bfloat16_rn(w1 - __bfloat162float(h1));
        }
        int nprime = (n & 7)*4 + (n >> 3);
        dst[((((size_t)t*nch + c)*2 + hf)*8 + j)*32 + nprime] = pack_bf16x2(p0, p1);
    }
}

// ---------------- BN split pass: y(fp32) -> BN+LReLU -> packed hi/lo ----------------
__global__ __launch_bounds__(256)
void split_kernel(const float* __restrict__ y,
                  uint32_t* __restrict__ ph, uint32_t* __restrict__ pl)
{
    int idx = blockIdx.x * 256 + threadIdx.x;      // over BB*16*SPA
    int r = idx % SPA;
    int p = (idx / SPA) % 16;
    int b = idx / (16*SPA);

    float v0 = y[((size_t)b*HID + 2*p    )*SPA + r];
    float v1 = y[((size_t)b*HID + 2*p + 1)*SPA + r];
    float2 s0 = g_ss[2*p], s1 = g_ss[2*p + 1];
    v0 = fmaf(s0.x, v0, s0.y); v0 = (v0 > 0.f) ? v0 : NEG*v0;
    v1 = fmaf(s1.x, v1, s1.y); v1 = (v1 > 0.f) ? v1 : NEG*v1;
    uint32_t hi, lo;
    split_pack(v0, v1, hi, lo);
    ph[idx] = hi;
    pl[idx] = lo;
}

// ---------------- implicit-GEMM conv3d via mma.sync (bf16 split) ----------------
#define SA_STRIDE 136
#define SW_STRIDE 40
#define SD_STRIDE 132

template<int CIN>
__global__ __launch_bounds__(256)
void conv_mma(const uint32_t* __restrict__ ph,
              const uint32_t* __restrict__ pl,
              const uint32_t* __restrict__ wp,
              float* __restrict__ out)
{
    constexpr int NCH = CIN / 16;
    constexpr int NPAIR = CIN / 2;
    constexpr int SW_U32 = 3*NCH*2*8*SW_STRIDE;

    extern __shared__ __align__(16) uint8_t smem[];
    uint32_t* sW  = (uint32_t*)smem;                 // [3][NCH][2][8][40]
    uint32_t* sAh = sW + SW_U32;                     // [NPAIR][136]
    uint32_t* sAl = sAh + NPAIR*SA_STRIDE;
    float*    sD  = (float*)smem;                    // epilogue overlay
    float*    sSum = sD + HID*SD_STRIDE;             // [32][8]
    float*    sSq  = sSum + 256;

    const int row = blockIdx.x;                  // 0..NROWS-1
    const int b = row / (DDISP*HH);
    const int d = (row / HH) % DDISP;
    const int h = row % HH;

    const int tid  = threadIdx.x;
    const int warp = tid >> 5;
    const int lane = tid & 31;
    const int g    = lane >> 2;
    const int p4   = lane & 3;
    const int m_base = warp * 16;
    const int HW = HH*WW;

    float acc[4][4];
#pragma unroll
    for (int nb = 0; nb < 4; nb++)
#pragma unroll
        for (int v = 0; v < 4; v++) acc[nb][v] = 0.f;

    // zero the pad slots once (never overwritten by staging)
    if (tid < 2*NPAIR) {
        const int p  = tid >> 1;
        const int ix = (tid & 1) ? 129 : 0;
        sAh[p*SA_STRIDE + ix] = 0;
        sAl[p*SA_STRIDE + ix] = 0;
    }

#pragma unroll 1
    for (int kd = 0; kd < 3; kd++) {
        const int dd = d + kd - 1;
        if (dd < 0 || dd >= DDISP) continue;
#pragma unroll 1
        for (int kh = 0; kh < 3; kh++) {
            const int hh2 = h + kh - 1;
            if (hh2 < 0 || hh2 >= HH) continue;

            __syncthreads();   // previous compute done before restage

            // ---- stage activation row: pure u32 copies (uint4 loads)
            for (int i = tid; i < NPAIR*32; i += 256) {
                const int p  = i >> 5;
                const int w4 = (i & 31) * 4;
                const size_t src = ((size_t)(b*NPAIR + p)*DDISP + dd)*HW + hh2*WW + w4;
                uint4 vh = *(const uint4*)&ph[src];
                uint4 vl = *(const uint4*)&pl[src];
                uint32_t* da = &sAh[p*SA_STRIDE + w4 + 1];
                uint32_t* dl = &sAl[p*SA_STRIDE + w4 + 1];
                da[0] = vh.x; da[1] = vh.y; da[2] = vh.z; da[3] = vh.w;
                dl[0] = vl.x; dl[1] = vl.y; dl[2] = vl.z; dl[3] = vl.w;
            }
            // ---- stage B fragments for the 3 kw taps of this (kd,kh)
            {
                const int t_base = (kd*3 + kh)*3;
                const uint32_t* src = wp + (size_t)t_base * (NCH*2*8*32);
                for (int i = tid; i < 3*NCH*2*8*32; i += 256) {
                    const int n  = i & 31;          // already-permuted position
                    const int j  = (i >> 5) & 7;
                    const int hf = (i >> 8) & 1;
                    const int cc = (i >> 9) % NCH;
                    const int kw = (i >> 9) / NCH;
                    sW[(((kw*NCH + cc)*2 + hf)*8 + j)*SW_STRIDE + n] = src[i];
                }
            }
            __syncthreads();

            // ---- compute: 3 kw taps x NCH chunks
#pragma unroll 1
            for (int kw = 0; kw < 3; kw++) {
#pragma unroll 1
                for (int c = 0; c < NCH; c++) {
                    const int bp  = c*8;
                    const int col = m_base + g + kw;
                    uint32_t ah[4], al[4];
                    ah[0] = sAh[(bp + p4    )*SA_STRIDE + col];
                    ah[1] = sAh[(bp + p4    )*SA_STRIDE + col + 8];
                    ah[2] = sAh[(bp + p4 + 4)*SA_STRIDE + col];
                    ah[3] = sAh[(bp + p4 + 4)*SA_STRIDE + col + 8];
                    al[0] = sAl[(bp + p4    )*SA_STRIDE + col];
                    al[1] = sAl[(bp + p4    )*SA_STRIDE + col + 8];
                    al[2] = sAl[(bp + p4 + 4)*SA_STRIDE + col];
                    al[3] = sAl[(bp + p4 + 4)*SA_STRIDE + col + 8];

                    // vectorized B: 4 x LDS.128 (n' permute makes nb-fragments contiguous)
                    const uint32_t* wb = sW + ((kw*NCH + c)*2)*8*SW_STRIDE;
                    uint4 bh0 = *(const uint4*)(wb + p4*SW_STRIDE + g*4);
                    uint4 bh1 = *(const uint4*)(wb + (p4 + 4)*SW_STRIDE + g*4);
                    uint4 bl0 = *(const uint4*)(wb + 8*SW_STRIDE + p4*SW_STRIDE + g*4);
                    uint4 bl1 = *(const uint4*)(wb + 8*SW_STRIDE + (p4 + 4)*SW_STRIDE + g*4);

                    mma16816(acc[0], ah, bh0.x, bh1.x);
                    mma16816(acc[0], ah, bl0.x, bl1.x);
                    mma16816(acc[0], al, bh0.x, bh1.x);
                    mma16816(acc[1], ah, bh0.y, bh1.y);
                    mma16816(acc[1], ah, bl0.y, bl1.y);
                    mma16816(acc[1], al, bh0.y, bh1.y);
                    mma16816(acc[2], ah, bh0.z, bh1.z);
                    mma16816(acc[2], ah, bl0.z, bl1.z);
                    mma16816(acc[2], al, bh0.z, bh1.z);
                    mma16816(acc[3], ah, bh0.w, bh1.w);
                    mma16816(acc[3], ah, bl0.w, bl1.w);
                    mma16816(acc[3], al, bh0.w, bh1.w);
                }
            }
        }
    }

    // ---- epilogue: smem transpose -> coalesced stores + fused BN partial sums
    __syncthreads();
#pragma unroll
    for (int nb = 0; nb < 4; nb++) {
        const int co = nb*8 + 2*p4;
        sD[(co    )*SD_STRIDE + m_base + g    ] = acc[nb][0];
        sD[(co + 1)*SD_STRIDE + m_base + g    ] = acc[nb][1];
        sD[(co    )*SD_STRIDE + m_base + g + 8] = acc[nb][2];
        sD[(co + 1)*SD_STRIDE + m_base + g + 8] = acc[nb][3];
    }
    __syncthreads();
    for (int i = tid; i < HID*32; i += 256) {
        const int co = i >> 5;
        const int q  = (i & 31) * 4;
        float4 v = *(const float4*)&sD[co*SD_STRIDE + q];
        *(float4*)&out[(((size_t)b*HID + co)*DDISP + d)*(HH*WW) + h*WW + q] = v;
    }
    {
        const int co = tid >> 3;
        const int sg = tid & 7;
        const float* rp = &sD[co*SD_STRIDE + sg*16];
        float s = 0.f, sq = 0.f;
#pragma unroll
        for (int j = 0; j < 16; j++) { float v = rp[j]; s += v; sq += v*v; }
        sSum[co*8 + sg] = s;
        sSq [co*8 + sg] = sq;
    }
    __syncthreads();
    if (tid < HID) {
        float S = 0.f, Q = 0.f;
#pragma unroll
        for (int k = 0; k < 8; k++) { S += sSum[tid*8 + k]; Q += sSq[tid*8 + k]; }
        g_rsum[(size_t)tid*NROWS + row] = S;
        g_rsq [(size_t)tid*NROWS + row] = Q;
    }
}

// ---------------- BN finalize: reduce per-row partials -> g_ss ----------------
__global__ __launch_bounds__(256)
void finalize2_kernel(const float* __restrict__ gamma,
                      const float* __restrict__ beta)
{
    const int ch = blockIdx.x;
    float s = 0.f, sq = 0.f;
    for (int r = threadIdx.x; r < NROWS; r += 256) {
        s  += g_rsum[(size_t)ch*NROWS + r];
        sq += g_rsq [(size_t)ch*NROWS + r];
    }
    __shared__ float rs[256], rq[256];
    rs[threadIdx.x] = s; rq[threadIdx.x] = sq;
    __syncthreads();
    for (int st = 128; st > 0; st >>= 1) {
        if (threadIdx.x < st) {
            rs[threadIdx.x] += rs[threadIdx.x + st];
            rq[threadIdx.x] += rq[threadIdx.x + st];
        }
        __syncthreads();
    }
    if (threadIdx.x == 0) {
        const float N = (float)(BB*SPA);
        float mean = rs[0] / N;
        float var  = fmaxf(rq[0] / N - mean*mean, 0.f);
        float scale = gamma[ch] * rsqrtf(var + EPSBN);
        g_ss[ch] = make_float2(scale, beta[ch] - mean*scale);
    }
}

// ---------------- final conv (32 -> 1), smem-tiled scalar ----------------
#define TD 2
#define TH 8
#define TW 16
#define CD 4
#define CH 10
#define CWD 18
#define CWP 19
#define CHUNK 4

__global__ __launch_bounds__(256)
void final_kernel(const float* __restrict__ x,
                  const float* __restrict__ wf,
                  const float* __restrict__ bf,
                  float* __restrict__ out)
{
    __shared__ float sIn[CHUNK][CD][CH][CWP];
    __shared__ float sw[HID*27];
    __shared__ float2 sss[HID];

    const int w0 = blockIdx.x * TW;
    const int h0 = blockIdx.y * TH;
    const int bz = blockIdx.z;
    const int b  = bz / (DDISP/TD);
    const int d0 = (bz % (DDISP/TD)) * TD;
    const int tid = threadIdx.x;

    const int tdz = tid >> 7;
    const int thy = (tid >> 4) & 7;
    const int twx = tid & 15;

    for (int i = tid; i < HID*27; i += 256) sw[i] = wf[i];
    if (tid < HID) sss[tid] = g_ss[tid];
    __syncthreads();

    float acc = 0.f;
    for (int c0 = 0; c0 < HID; c0 += CHUNK) {
        __syncthreads();
        for (int i = tid; i < CHUNK*CD*CH*CWD; i += 256) {
            int c  = i / (CD*CH*CWD);
            int r  = i % (CD*CH*CWD);
            int dz = r / (CH*CWD);
            int r2 = r % (CH*CWD);
            int hy = r2 / CWD;
            int wx = r2 % CWD;
            int gd = d0 - 1 + dz;
            int gh = h0 - 1 + hy;
            int gw = w0 - 1 + wx;
            float val = 0.f;
            if (gd >= 0 && gd < DDISP && gh >= 0 && gh < HH && gw >= 0 && gw < WW) {
                val = x[(((size_t)b*HID + (c0 + c))*DDISP + gd)*(HH*WW) + gh*WW + gw];
                float2 s = sss[c0 + c];
                val = fmaf(s.x, val, s.y);
                val = (val > 0.f) ? val : NEG*val;
            }
            sIn[c][dz][hy][wx] = val;
        }
        __syncthreads();

#pragma unroll 1
        for (int c = 0; c < CHUNK; c++) {
#pragma unroll
            for (int kd = 0; kd < 3; kd++) {
#pragma unroll
                for (int kh = 0; kh < 3; kh++) {
#pragma unroll
                    for (int kw = 0; kw < 3; kw++) {
                        acc = fmaf(sw[(c0 + c)*27 + (kd*3 + kh)*3 + kw],
                                   sIn[c][tdz + kd][thy + kh][twx + kw], acc);
                    }
                }
            }
        }
    }

    const int gd = d0 + tdz, gh = h0 + thy, gw = w0 + twx;
    out[(((size_t)b*DDISP + gd)*HH + gh)*WW + gw] = acc + bf[0];
}

// ---------------- launch ----------------
extern "C" void kernel_launch(void* const* d_in, const int* in_sizes, int n_in,
                              void* d_out, int out_size)
{
    const float* left  = (const float*)d_in[0];
    const float* right = (const float*)d_in[1];
    const float* w1 = (const float*)d_in[2];
    const float* g1 = (const float*)d_in[3];
    const float* b1 = (const float*)d_in[4];
    const float* w2 = (const float*)d_in[5];
    const float* g2 = (const float*)d_in[6];
    const float* b2 = (const float*)d_in[7];
    const float* w3 = (const float*)d_in[8];
    const float* g3 = (const float*)d_in[9];
    const float* b3 = (const float*)d_in[10];
    const float* w4 = (const float*)d_in[11];
    const float* g4 = (const float*)d_in[12];
    const float* b4 = (const float*)d_in[13];
    const float* wf = (const float*)d_in[14];
    const float* bf = (const float*)d_in[15];
    float* out = (float*)d_out;
    (void)in_sizes; (void)n_in; (void)out_size;

    float *buf;
    uint32_t *wp, *phb, *plb;
    cudaGetSymbolAddress((void**)&buf, g_buf0);
    cudaGetSymbolAddress((void**)&wp,  g_wp);
    cudaGetSymbolAddress((void**)&phb, g_ph);
    cudaGetSymbolAddress((void**)&plb, g_pl);
    uint32_t* ph0 = phb;        uint32_t* pl0 = plb;
    uint32_t* ph1 = phb + PKE;  uint32_t* pl1 = plb + PKE;

    // dynamic smem sizes (bytes) — identical to the proven R9 footprint
    const int SD_BYTES = (HID*SD_STRIDE + 512)*4;
    const int SM16_raw = (3*1*2*8*SW_STRIDE + 2*8*SA_STRIDE)*4;
    const int SM32_raw = (3*2*2*8*SW_STRIDE + 2*16*SA_STRIDE)*4;
    const int SMEM16 = (SM16_raw > SD_BYTES) ? SM16_raw : SD_BYTES;
    const int SMEM32 = (SM32_raw > SD_BYTES) ? SM32_raw : SD_BYTES;

    cudaFuncSetAttribute(conv_mma<16>, cudaFuncAttributeMaxDynamicSharedMemorySize, SMEM16);
    cudaFuncSetAttribute(conv_mma<32>, cudaFuncAttributeMaxDynamicSharedMemorySize, SMEM32);

    dim3 cgrid(WW/TW, HH/TH, BB*(DDISP/TD));
    const int SPLIT_GRID = PKE/256;

    wpack_kernel<<<27, 256>>>(w1, 16, wp + 0*WP_LAYER_U32);
    wpack_kernel<<<27, 256>>>(w2, 32, wp + 1*WP_LAYER_U32);
    wpack_kernel<<<27, 256>>>(w3, 32, wp + 2*WP_LAYER_U32);
    wpack_kernel<<<27, 256>>>(w4, 32, wp + 3*WP_LAYER_U32);

    vol_pack_kernel<<<BB*8*HH, 128>>>(left, right, ph0, pl0);

    conv_mma<16><<<NROWS, 256, SMEM16>>>(ph0, pl0, wp + 0*WP_LAYER_U32, buf);
    finalize2_kernel<<<HID, 256>>>(g1, b1);
    split_kernel<<<SPLIT_GRID, 256>>>(buf, ph1, pl1);

    conv_mma<32><<<NROWS, 256, SMEM32>>>(ph1, pl1, wp + 1*WP_LAYER_U32, buf);
    finalize2_kernel<<<HID, 256>>>(g2, b2);
    split_kernel<<<SPLIT_GRID, 256>>>(buf, ph0, pl0);

    conv_mma<32><<<NROWS, 256, SMEM32>>>(ph0, pl0, wp + 2*WP_LAYER_U32, buf);
    finalize2_kernel<<<HID, 256>>>(g3, b3);
    split_kernel<<<SPLIT_GRID, 256>>>(buf, ph1, pl1);

    conv_mma<32><<<NROWS, 256, SMEM32>>>(ph1, pl1, wp + 3*WP_LAYER_U32, buf);
    finalize2_kernel<<<HID, 256>>>(g4, b4);

    final_kernel<<<cgrid, 256>>>(buf, wf, bf, out);
}

// round 15
// speedup vs baseline: 1.4415x; 1.2049x over previous
#include <cuda_runtime.h>
#include <cuda_fp16.h>
#include <cstdint>

// ---------------- problem constants ----------------
#define BB    2
#define CFEAT 128
#define HH    64
#define WW    128
#define GG    16
#define CPG   8
#define DDISP 48
#define HID   32
#define NEG   0.2f
#define EPSBN 1e-5f

#define SPA    (DDISP*HH*WW)
#define X_ELEMS (BB*HID*SPA)
#define NROWS  (BB*DDISP*HH)          // 6144
#define PKE    (BB*16*SPA)

// ---------------- scratch ----------------
__device__ float    g_buf0[X_ELEMS];
__device__ uint32_t g_ph[2*PKE];              // fp16 hi pairs
__device__ uint32_t g_pl[2*PKE];              // fp16 lo (residual) pairs
__device__ float    g_rsum[HID*NROWS];
__device__ float    g_rsq [HID*NROWS];
__device__ float2   g_ss  [HID];
// packed fp16 weight fragments: [tap 27][chunk NCH][j 8][n' 32], n' = (n&7)*4 + (n>>3)
#define WP_LAYER_U32 (27*2*8*32)
__device__ uint32_t g_wp[4*WP_LAYER_U32];

// ---------------- mma.sync m16n8k16 fp16 ----------------
__device__ __forceinline__ void mma16816(float d[4], const uint32_t a[4],
                                         uint32_t b0, uint32_t b1)
{
    asm volatile(
        "mma.sync.aligned.m16n8k16.row.col.f32.f16.f16.f32 "
        "{%0,%1,%2,%3}, {%4,%5,%6,%7}, {%8,%9}, {%0,%1,%2,%3};\n"
        : "+f"(d[0]), "+f"(d[1]), "+f"(d[2]), "+f"(d[3])
        : "r"(a[0]), "r"(a[1]), "r"(a[2]), "r"(a[3]), "r"(b0), "r"(b1));
}

__device__ __forceinline__ uint32_t pack_f16x2(__half lo, __half hi)
{
    unsigned short u0 = *reinterpret_cast<unsigned short*>(&lo);
    unsigned short u1 = *reinterpret_cast<unsigned short*>(&hi);
    return (uint32_t)u0 | ((uint32_t)u1 << 16);
}

__device__ __forceinline__ void split_pack(float v0, float v1,
                                           uint32_t& hi, uint32_t& lo)
{
    __half h0 = __float2half_rn(v0);
    __half h1 = __float2half_rn(v1);
    __half l0 = __float2half_rn(v0 - __half2float(h0));
    __half l1 = __float2half_rn(v1 - __half2float(h1));
    hi = pack_f16x2(h0, h1);
    lo = pack_f16x2(l0, l1);
}

// ---------------- volume build, emitting packed hi/lo directly ----------------
__global__ void vol_pack_kernel(const float* __restrict__ left,
                                const float* __restrict__ right,
                                uint32_t* __restrict__ ph,
                                uint32_t* __restrict__ pl)
{
    int h = blockIdx.x % HH;
    int p = (blockIdx.x / HH) % 8;
    int b = blockIdx.x / (HH*8);
    int w = threadIdx.x;                       // 128

    __shared__ float sR[16][WW];
    float l[16];
    const float* lp = left  + (((size_t)b*CFEAT + p*16)*HH + h)*WW + w;
    const float* rp = right + (((size_t)b*CFEAT + p*16)*HH + h)*WW + w;
#pragma unroll
    for (int c = 0; c < 16; c++) {
        l[c]     = lp[(size_t)c*HH*WW];
        sR[c][w] = rp[(size_t)c*HH*WW];
    }
    __syncthreads();

    uint32_t* hp  = ph + ((size_t)(b*8 + p)*DDISP)*(HH*WW) + h*WW + w;
    uint32_t* lp2 = pl + ((size_t)(b*8 + p)*DDISP)*(HH*WW) + h*WW + w;
    for (int d = 0; d < DDISP; d++) {
        float s0 = 0.f, s1 = 0.f;
        if (w >= d) {
            int ws = w - d;
#pragma unroll
            for (int c = 0; c < 8; c++)  s0 += l[c]*sR[c][ws];
#pragma unroll
            for (int c = 8; c < 16; c++) s1 += l[c]*sR[c][ws];
        }
        s0 *= (1.0f/CPG); s1 *= (1.0f/CPG);
        uint32_t hi, lo;
        split_pack(s0, s1, hi, lo);
        hp [(size_t)d*HH*WW] = hi;
        lp2[(size_t)d*HH*WW] = lo;
    }
}

// ---------------- weight fragment pre-pack (fp16, n-permuted for LDS.128) ----------------
__global__ void wpack_kernel(const float* __restrict__ wg, int cin,
                             uint32_t* __restrict__ dst)
{
    const int t = blockIdx.x;            // 0..26
    const int nch = cin / 16;
    const int elems = nch * 256;         // 8 j x 32 n per chunk
    for (int i = threadIdx.x; i < elems; i += 256) {
        int n  = i & 31;
        int j  = (i >> 5) & 7;
        int c  = i >> 8;
        int ci0 = c*16 + 2*j;
        float w0 = wg[((size_t)n*cin + ci0    )*27 + t];
        float w1 = wg[((size_t)n*cin + ci0 + 1)*27 + t];
        __half p0 = __float2half_rn(w0);
        __half p1 = __float2half_rn(w1);
        int nprime = (n & 7)*4 + (n >> 3);
        dst[(((size_t)t*nch + c)*8 + j)*32 + nprime] = pack_f16x2(p0, p1);
    }
}

// ---------------- BN split pass: y(fp32) -> BN+LReLU -> packed hi/lo ----------------
__global__ __launch_bounds__(256)
void split_kernel(const float* __restrict__ y,
                  uint32_t* __restrict__ ph, uint32_t* __restrict__ pl)
{
    int idx = blockIdx.x * 256 + threadIdx.x;      // over BB*16*SPA
    int r = idx % SPA;
    int p = (idx / SPA) % 16;
    int b = idx / (16*SPA);

    float v0 = y[((size_t)b*HID + 2*p    )*SPA + r];
    float v1 = y[((size_t)b*HID + 2*p + 1)*SPA + r];
    float2 s0 = g_ss[2*p], s1 = g_ss[2*p + 1];
    v0 = fmaf(s0.x, v0, s0.y); v0 = (v0 > 0.f) ? v0 : NEG*v0;
    v1 = fmaf(s1.x, v1, s1.y); v1 = (v1 > 0.f) ? v1 : NEG*v1;
    uint32_t hi, lo;
    split_pack(v0, v1, hi, lo);
    ph[idx] = hi;
    pl[idx] = lo;
}

// ---------------- implicit-GEMM conv3d via mma.sync (fp16 2-term split) ----------------
#define SA_STRIDE 136
#define SW_STRIDE 40
#define SD_STRIDE 132

template<int CIN>
__global__ __launch_bounds__(256)
void conv_mma(const uint32_t* __restrict__ ph,
              const uint32_t* __restrict__ pl,
              const uint32_t* __restrict__ wp,
              float* __restrict__ out)
{
    constexpr int NCH = CIN / 16;
    constexpr int NPAIR = CIN / 2;
    constexpr int SW_U32 = 3*NCH*8*SW_STRIDE;      // single-half weights

    extern __shared__ __align__(16) uint8_t smem[];
    uint32_t* sW  = (uint32_t*)smem;                 // [3][NCH][8][40]
    uint32_t* sAh = sW + SW_U32;                     // [NPAIR][136]
    uint32_t* sAl = sAh + NPAIR*SA_STRIDE;
    float*    sD  = (float*)smem;                    // epilogue overlay
    float*    sSum = sD + HID*SD_STRIDE;             // [32][8]
    float*    sSq  = sSum + 256;

    const int row = blockIdx.x;                  // 0..NROWS-1
    const int b = row / (DDISP*HH);
    const int d = (row / HH) % DDISP;
    const int h = row % HH;

    const int tid  = threadIdx.x;
    const int warp = tid >> 5;
    const int lane = tid & 31;
    const int g    = lane >> 2;
    const int p4   = lane & 3;
    const int m_base = warp * 16;
    const int HW = HH*WW;

    float acc[4][4];
#pragma unroll
    for (int nb = 0; nb < 4; nb++)
#pragma unroll
        for (int v = 0; v < 4; v++) acc[nb][v] = 0.f;

    // zero the pad slots once (never overwritten by staging)
    if (tid < 2*NPAIR) {
        const int p  = tid >> 1;
        const int ix = (tid & 1) ? 129 : 0;
        sAh[p*SA_STRIDE + ix] = 0;
        sAl[p*SA_STRIDE + ix] = 0;
    }

#pragma unroll 1
    for (int kd = 0; kd < 3; kd++) {
        const int dd = d + kd - 1;
        if (dd < 0 || dd >= DDISP) continue;
#pragma unroll 1
        for (int kh = 0; kh < 3; kh++) {
            const int hh2 = h + kh - 1;
            if (hh2 < 0 || hh2 >= HH) continue;

            __syncthreads();   // previous compute done before restage

            // ---- stage activation row: pure u32 copies (uint4 loads)
            for (int i = tid; i < NPAIR*32; i += 256) {
                const int p  = i >> 5;
                const int w4 = (i & 31) * 4;
                const size_t src = ((size_t)(b*NPAIR + p)*DDISP + dd)*HW + hh2*WW + w4;
                uint4 vh = *(const uint4*)&ph[src];
                uint4 vl = *(const uint4*)&pl[src];
                uint32_t* da = &sAh[p*SA_STRIDE + w4 + 1];
                uint32_t* dl = &sAl[p*SA_STRIDE + w4 + 1];
                da[0] = vh.x; da[1] = vh.y; da[2] = vh.z; da[3] = vh.w;
                dl[0] = vl.x; dl[1] = vl.y; dl[2] = vl.z; dl[3] = vl.w;
            }
            // ---- stage B fragments for the 3 kw taps of this (kd,kh)
            {
                const int t_base = (kd*3 + kh)*3;
                const uint32_t* src = wp + (size_t)t_base * (NCH*8*32);
                for (int i = tid; i < 3*NCH*8*32; i += 256) {
                    const int n  = i & 31;          // already-permuted position
                    const int j  = (i >> 5) & 7;
                    const int cc = (i >> 8) % NCH;
                    const int kw = (i >> 8) / NCH;
                    sW[((kw*NCH + cc)*8 + j)*SW_STRIDE + n] = src[i];
                }
            }
            __syncthreads();

            // ---- compute: 3 kw taps x NCH chunks, 2 MMAs per nb (hi + residual)
#pragma unroll 1
            for (int kw = 0; kw < 3; kw++) {
#pragma unroll 1
                for (int c = 0; c < NCH; c++) {
                    const int bp  = c*8;
                    const int col = m_base + g + kw;
                    uint32_t ah[4], al[4];
                    ah[0] = sAh[(bp + p4    )*SA_STRIDE + col];
                    ah[1] = sAh[(bp + p4    )*SA_STRIDE + col + 8];
                    ah[2] = sAh[(bp + p4 + 4)*SA_STRIDE + col];
                    ah[3] = sAh[(bp + p4 + 4)*SA_STRIDE + col + 8];
                    al[0] = sAl[(bp + p4    )*SA_STRIDE + col];
                    al[1] = sAl[(bp + p4    )*SA_STRIDE + col + 8];
                    al[2] = sAl[(bp + p4 + 4)*SA_STRIDE + col];
                    al[3] = sAl[(bp + p4 + 4)*SA_STRIDE + col + 8];

                    // vectorized B: 2 x LDS.128
                    const uint32_t* wb = sW + (kw*NCH + c)*8*SW_STRIDE;
                    uint4 bh0 = *(const uint4*)(wb + p4*SW_STRIDE + g*4);
                    uint4 bh1 = *(const uint4*)(wb + (p4 + 4)*SW_STRIDE + g*4);

                    mma16816(acc[0], ah, bh0.x, bh1.x);
                    mma16816(acc[0], al, bh0.x, bh1.x);
                    mma16816(acc[1], ah, bh0.y, bh1.y);
                    mma16816(acc[1], al, bh0.y, bh1.y);
                    mma16816(acc[2], ah, bh0.z, bh1.z);
                    mma16816(acc[2], al, bh0.z, bh1.z);
                    mma16816(acc[3], ah, bh0.w, bh1.w);
                    mma16816(acc[3], al, bh0.w, bh1.w);
                }
            }
        }
    }

    // ---- epilogue: smem transpose -> coalesced stores + fused BN partial sums
    __syncthreads();
#pragma unroll
    for (int nb = 0; nb < 4; nb++) {
        const int co = nb*8 + 2*p4;
        sD[(co    )*SD_STRIDE + m_base + g    ] = acc[nb][0];
        sD[(co + 1)*SD_STRIDE + m_base + g    ] = acc[nb][1];
        sD[(co    )*SD_STRIDE + m_base + g + 8] = acc[nb][2];
        sD[(co + 1)*SD_STRIDE + m_base + g + 8] = acc[nb][3];
    }
    __syncthreads();
    for (int i = tid; i < HID*32; i += 256) {
        const int co = i >> 5;
        const int q  = (i & 31) * 4;
        float4 v = *(const float4*)&sD[co*SD_STRIDE + q];
        *(float4*)&out[(((size_t)b*HID + co)*DDISP + d)*(HH*WW) + h*WW + q] = v;
    }
    {
        const int co = tid >> 3;
        const int sg = tid & 7;
        const float* rp = &sD[co*SD_STRIDE + sg*16];
        float s = 0.f, sq = 0.f;
#pragma unroll
        for (int j = 0; j < 16; j++) { float v = rp[j]; s += v; sq += v*v; }
        sSum[co*8 + sg] = s;
        sSq [co*8 + sg] = sq;
    }
    __syncthreads();
    if (tid < HID) {
        float S = 0.f, Q = 0.f;
#pragma unroll
        for (int k = 0; k < 8; k++) { S += sSum[tid*8 + k]; Q += sSq[tid*8 + k]; }
        g_rsum[(size_t)tid*NROWS + row] = S;
        g_rsq [(size_t)tid*NROWS + row] = Q;
    }
}

// ---------------- BN finalize: reduce per-row partials -> g_ss ----------------
__global__ __launch_bounds__(256)
void finalize2_kernel(const float* __restrict__ gamma,
                      const float* __restrict__ beta)
{
    const int ch = blockIdx.x;
    float s = 0.f, sq = 0.f;
    for (int r = threadIdx.x; r < NROWS; r += 256) {
        s  += g_rsum[(size_t)ch*NROWS + r];
        sq += g_rsq [(size_t)ch*NROWS + r];
    }
    __shared__ float rs[256], rq[256];
    rs[threadIdx.x] = s; rq[threadIdx.x] = sq;
    __syncthreads();
    for (int st = 128; st > 0; st >>= 1) {
        if (threadIdx.x < st) {
            rs[threadIdx.x] += rs[threadIdx.x + st];
            rq[threadIdx.x] += rq[threadIdx.x + st];
        }
        __syncthreads();
    }
    if (threadIdx.x == 0) {
        const float N = (float)(BB*SPA);
        float mean = rs[0] / N;
        float var  = fmaxf(rq[0] / N - mean*mean, 0.f);
        float scale = gamma[ch] * rsqrtf(var + EPSBN);
        g_ss[ch] = make_float2(scale, beta[ch] - mean*scale);
    }
}

// ---------------- final conv (32 -> 1), smem-tiled scalar ----------------
#define TD 2
#define TH 8
#define TW 16
#define CD 4
#define CH 10
#define CWD 18
#define CWP 19
#define CHUNK 4

__global__ __launch_bounds__(256)
void final_kernel(const float* __restrict__ x,
                  const float* __restrict__ wf,
                  const float* __restrict__ bf,
                  float* __restrict__ out)
{
    __shared__ float sIn[CHUNK][CD][CH][CWP];
    __shared__ float sw[HID*27];
    __shared__ float2 sss[HID];

    const int w0 = blockIdx.x * TW;
    const int h0 = blockIdx.y * TH;
    const int bz = blockIdx.z;
    const int b  = bz / (DDISP/TD);
    const int d0 = (bz % (DDISP/TD)) * TD;
    const int tid = threadIdx.x;

    const int tdz = tid >> 7;
    const int thy = (tid >> 4) & 7;
    const int twx = tid & 15;

    for (int i = tid; i < HID*27; i += 256) sw[i] = wf[i];
    if (tid < HID) sss[tid] = g_ss[tid];
    __syncthreads();

    float acc = 0.f;
    for (int c0 = 0; c0 < HID; c0 += CHUNK) {
        __syncthreads();
        for (int i = tid; i < CHUNK*CD*CH*CWD; i += 256) {
            int c  = i / (CD*CH*CWD);
            int r  = i % (CD*CH*CWD);
            int dz = r / (CH*CWD);
            int r2 = r % (CH*CWD);
            int hy = r2 / CWD;
            int wx = r2 % CWD;
            int gd = d0 - 1 + dz;
            int gh = h0 - 1 + hy;
            int gw = w0 - 1 + wx;
            float val = 0.f;
            if (gd >= 0 && gd < DDISP && gh >= 0 && gh < HH && gw >= 0 && gw < WW) {
                val = x[(((size_t)b*HID + (c0 + c))*DDISP + gd)*(HH*WW) + gh*WW + gw];
                float2 s = sss[c0 + c];
                val = fmaf(s.x, val, s.y);
                val = (val > 0.f) ? val : NEG*val;
            }
            sIn[c][dz][hy][wx] = val;
        }
        __syncthreads();

#pragma unroll 1
        for (int c = 0; c < CHUNK; c++) {
#pragma unroll
            for (int kd = 0; kd < 3; kd++) {
#pragma unroll
                for (int kh = 0; kh < 3; kh++) {
#pragma unroll
                    for (int kw = 0; kw < 3; kw++) {
                        acc = fmaf(sw[(c0 + c)*27 + (kd*3 + kh)*3 + kw],
                                   sIn[c][tdz + kd][thy + kh][twx + kw], acc);
                    }
                }
            }
        }
    }

    const int gd = d0 + tdz, gh = h0 + thy, gw = w0 + twx;
    out[(((size_t)b*DDISP + gd)*HH + gh)*WW + gw] = acc + bf[0];
}

// ---------------- launch ----------------
extern "C" void kernel_launch(void* const* d_in, const int* in_sizes, int n_in,
                              void* d_out, int out_size)
{
    const float* left  = (const float*)d_in[0];
    const float* right = (const float*)d_in[1];
    const float* w1 = (const float*)d_in[2];
    const float* g1 = (const float*)d_in[3];
    const float* b1 = (const float*)d_in[4];
    const float* w2 = (const float*)d_in[5];
    const float* g2 = (const float*)d_in[6];
    const float* b2 = (const float*)d_in[7];
    const float* w3 = (const float*)d_in[8];
    const float* g3 = (const float*)d_in[9];
    const float* b3 = (const float*)d_in[10];
    const float* w4 = (const float*)d_in[11];
    const float* g4 = (const float*)d_in[12];
    const float* b4 = (const float*)d_in[13];
    const float* wf = (const float*)d_in[14];
    const float* bf = (const float*)d_in[15];
    float* out = (float*)d_out;
    (void)in_sizes; (void)n_in; (void)out_size;

    float *buf;
    uint32_t *wp, *phb, *plb;
    cudaGetSymbolAddress((void**)&buf, g_buf0);
    cudaGetSymbolAddress((void**)&wp,  g_wp);
    cudaGetSymbolAddress((void**)&phb, g_ph);
    cudaGetSymbolAddress((void**)&plb, g_pl);
    uint32_t* ph0 = phb;        uint32_t* pl0 = plb;
    uint32_t* ph1 = phb + PKE;  uint32_t* pl1 = plb + PKE;

    // dynamic smem sizes (bytes)
    const int SD_BYTES = (HID*SD_STRIDE + 512)*4;
    const int SM16_raw = (3*1*8*SW_STRIDE + 2*8*SA_STRIDE)*4;
    const int SM32_raw = (3*2*8*SW_STRIDE + 2*16*SA_STRIDE)*4;
    const int SMEM16 = (SM16_raw > SD_BYTES) ? SM16_raw : SD_BYTES;
    const int SMEM32 = (SM32_raw > SD_BYTES) ? SM32_raw : SD_BYTES;

    cudaFuncSetAttribute(conv_mma<16>, cudaFuncAttributeMaxDynamicSharedMemorySize, SMEM16);
    cudaFuncSetAttribute(conv_mma<32>, cudaFuncAttributeMaxDynamicSharedMemorySize, SMEM32);

    dim3 cgrid(WW/TW, HH/TH, BB*(DDISP/TD));
    const int SPLIT_GRID = PKE/256;

    wpack_kernel<<<27, 256>>>(w1, 16, wp + 0*WP_LAYER_U32);
    wpack_kernel<<<27, 256>>>(w2, 32, wp + 1*WP_LAYER_U32);
    wpack_kernel<<<27, 256>>>(w3, 32, wp + 2*WP_LAYER_U32);
    wpack_kernel<<<27, 256>>>(w4, 32, wp + 3*WP_LAYER_U32);

    vol_pack_kernel<<<BB*8*HH, 128>>>(left, right, ph0, pl0);

    conv_mma<16><<<NROWS, 256, SMEM16>>>(ph0, pl0, wp + 0*WP_LAYER_U32, buf);
    finalize2_kernel<<<HID, 256>>>(g1, b1);
    split_kernel<<<SPLIT_GRID, 256>>>(buf, ph1, pl1);

    conv_mma<32><<<NROWS, 256, SMEM32>>>(ph1, pl1, wp + 1*WP_LAYER_U32, buf);
    finalize2_kernel<<<HID, 256>>>(g2, b2);
    split_kernel<<<SPLIT_GRID, 256>>>(buf, ph0, pl0);

    conv_mma<32><<<NROWS, 256, SMEM32>>>(ph0, pl0, wp + 2*WP_LAYER_U32, buf);
    finalize2_kernel<<<HID, 256>>>(g3, b3);
    split_kernel<<<SPLIT_GRID, 256>>>(buf, ph1, pl1);

    conv_mma<32><<<NROWS, 256, SMEM32>>>(ph1, pl1, wp + 3*WP_LAYER_U32, buf);
    finalize2_kernel<<<HID, 256>>>(g4, b4);

    final_kernel<<<cgrid, 256>>>(buf, wf, bf, out);
}

// round 16
// speedup vs baseline: 1.5830x; 1.0981x over previous
#include <cuda_runtime.h>
#include <cuda_fp16.h>
#include <cstdint>

// ---------------- problem constants ----------------
#define BB    2
#define CFEAT 128
#define HH    64
#define WW    128
#define GG    16
#define CPG   8
#define DDISP 48
#define HID   32
#define NEG   0.2f
#define EPSBN 1e-5f

#define SPA    (DDISP*HH*WW)
#define X_ELEMS (BB*HID*SPA)
#define NROWS  (BB*DDISP*HH)          // 6144
#define PKE    (BB*16*SPA)

// ---------------- scratch ----------------
__device__ float    g_buf0[X_ELEMS];
__device__ uint32_t g_ph[2*PKE];              // fp16 hi pairs
__device__ uint32_t g_pl[2*PKE];              // fp16 lo (residual) pairs
__device__ float    g_rsum[HID*NROWS];
__device__ float    g_rsq [HID*NROWS];
__device__ float2   g_ss  [HID];
// packed fp16 weight fragments: [tap 27][chunk NCH][j 8][n' 32], n' = (n&7)*4 + (n>>3)
#define WP_LAYER_U32 (27*2*8*32)
__device__ uint32_t g_wp[4*WP_LAYER_U32];

// ---------------- mma.sync / cp.async helpers ----------------
__device__ __forceinline__ void mma16816(float d[4], const uint32_t a[4],
                                         uint32_t b0, uint32_t b1)
{
    asm volatile(
        "mma.sync.aligned.m16n8k16.row.col.f32.f16.f16.f32 "
        "{%0,%1,%2,%3}, {%4,%5,%6,%7}, {%8,%9}, {%0,%1,%2,%3};\n"
        : "+f"(d[0]), "+f"(d[1]), "+f"(d[2]), "+f"(d[3])
        : "r"(a[0]), "r"(a[1]), "r"(a[2]), "r"(a[3]), "r"(b0), "r"(b1));
}
#define CP_ASYNC16(dst_smem_u32addr, src_gptr) \
    asm volatile("cp.async.cg.shared.global [%0], [%1], 16;" \
                 :: "r"(dst_smem_u32addr), "l"(src_gptr) : "memory")
#define CP_COMMIT() asm volatile("cp.async.commit_group;" ::: "memory")
#define CP_WAIT0()  asm volatile("cp.async.wait_group 0;" ::: "memory")
#define CP_WAIT1()  asm volatile("cp.async.wait_group 1;" ::: "memory")

__device__ __forceinline__ uint32_t pack_f16x2(__half lo, __half hi)
{
    unsigned short u0 = *reinterpret_cast<unsigned short*>(&lo);
    unsigned short u1 = *reinterpret_cast<unsigned short*>(&hi);
    return (uint32_t)u0 | ((uint32_t)u1 << 16);
}

__device__ __forceinline__ void split_pack(float v0, float v1,
                                           uint32_t& hi, uint32_t& lo)
{
    __half h0 = __float2half_rn(v0);
    __half h1 = __float2half_rn(v1);
    __half l0 = __float2half_rn(v0 - __half2float(h0));
    __half l1 = __float2half_rn(v1 - __half2float(h1));
    hi = pack_f16x2(h0, h1);
    lo = pack_f16x2(l0, l1);
}

// ---------------- volume build, emitting packed hi/lo directly ----------------
__global__ void vol_pack_kernel(const float* __restrict__ left,
                                const float* __restrict__ right,
                                uint32_t* __restrict__ ph,
                                uint32_t* __restrict__ pl)
{
    int h = blockIdx.x % HH;
    int p = (blockIdx.x / HH) % 8;
    int b = blockIdx.x / (HH*8);
    int w = threadIdx.x;                       // 128

    __shared__ float sR[16][WW];
    float l[16];
    const float* lp = left  + (((size_t)b*CFEAT + p*16)*HH + h)*WW + w;
    const float* rp = right + (((size_t)b*CFEAT + p*16)*HH + h)*WW + w;
#pragma unroll
    for (int c = 0; c < 16; c++) {
        l[c]     = lp[(size_t)c*HH*WW];
        sR[c][w] = rp[(size_t)c*HH*WW];
    }
    __syncthreads();

    uint32_t* hp  = ph + ((size_t)(b*8 + p)*DDISP)*(HH*WW) + h*WW + w;
    uint32_t* lp2 = pl + ((size_t)(b*8 + p)*DDISP)*(HH*WW) + h*WW + w;
    for (int d = 0; d < DDISP; d++) {
        float s0 = 0.f, s1 = 0.f;
        if (w >= d) {
            int ws = w - d;
#pragma unroll
            for (int c = 0; c < 8; c++)  s0 += l[c]*sR[c][ws];
#pragma unroll
            for (int c = 8; c < 16; c++) s1 += l[c]*sR[c][ws];
        }
        s0 *= (1.0f/CPG); s1 *= (1.0f/CPG);
        uint32_t hi, lo;
        split_pack(s0, s1, hi, lo);
        hp [(size_t)d*HH*WW] = hi;
        lp2[(size_t)d*HH*WW] = lo;
    }
}

// ---------------- weight fragment pre-pack (fp16, n-permuted) ----------------
__global__ void wpack_kernel(const float* __restrict__ wg, int cin,
                             uint32_t* __restrict__ dst)
{
    const int t = blockIdx.x;            // 0..26
    const int nch = cin / 16;
    const int elems = nch * 256;
    for (int i = threadIdx.x; i < elems; i += 256) {
        int n  = i & 31;
        int j  = (i >> 5) & 7;
        int c  = i >> 8;
        int ci0 = c*16 + 2*j;
        float w0 = wg[((size_t)n*cin + ci0    )*27 + t];
        float w1 = wg[((size_t)n*cin + ci0 + 1)*27 + t];
        __half p0 = __float2half_rn(w0);
        __half p1 = __float2half_rn(w1);
        int nprime = (n & 7)*4 + (n >> 3);
        dst[(((size_t)t*nch + c)*8 + j)*32 + nprime] = pack_f16x2(p0, p1);
    }
}

// ---------------- BN split pass ----------------
__global__ __launch_bounds__(256)
void split_kernel(const float* __restrict__ y,
                  uint32_t* __restrict__ ph, uint32_t* __restrict__ pl)
{
    int idx = blockIdx.x * 256 + threadIdx.x;
    int r = idx % SPA;
    int p = (idx / SPA) % 16;
    int b = idx / (16*SPA);

    float v0 = y[((size_t)b*HID + 2*p    )*SPA + r];
    float v1 = y[((size_t)b*HID + 2*p + 1)*SPA + r];
    float2 s0 = g_ss[2*p], s1 = g_ss[2*p + 1];
    v0 = fmaf(s0.x, v0, s0.y); v0 = (v0 > 0.f) ? v0 : NEG*v0;
    v1 = fmaf(s1.x, v1, s1.y); v1 = (v1 > 0.f) ? v1 : NEG*v1;
    uint32_t hi, lo;
    split_pack(v0, v1, hi, lo);
    ph[idx] = hi;
    pl[idx] = lo;
}

// ---------------- cp.async double-buffered implicit-GEMM conv3d ----------------
#define SA_STRIDE 136      // u32 per ci-pair row; data at +4, pads at 3 and 132
#define SW_STRIDE 40
#define SD_STRIDE 132

template<int CIN>
__global__ __launch_bounds__(256)
void conv_mma(const uint32_t* __restrict__ ph,
              const uint32_t* __restrict__ pl,
              const uint32_t* __restrict__ wp,
              float* __restrict__ out)
{
    constexpr int NCH   = CIN / 16;
    constexpr int NPAIR = CIN / 2;
    constexpr int SWBUF = 3*NCH*8*SW_STRIDE;       // u32 per B buffer
    constexpr int ABUF  = NPAIR*SA_STRIDE;         // u32 per A array buffer
    constexpr int NB4   = 3*NCH*8*8;               // B uint4 per tap group

    extern __shared__ __align__(16) uint8_t smem[];
    uint32_t* sW  = (uint32_t*)smem;               // [2][SWBUF]
    uint32_t* sAh = sW + 2*SWBUF;                  // [2][ABUF]
    uint32_t* sAl = sAh + 2*ABUF;                  // [2][ABUF]
    float*    sD  = (float*)smem;                  // epilogue overlay
    float*    sSum = sD + HID*SD_STRIDE;
    float*    sSq  = sSum + 256;

    const uint32_t smem_u = (uint32_t)__cvta_generic_to_shared(smem);
    const uint32_t sW_u   = smem_u;
    const uint32_t sAh_u  = smem_u + 2*SWBUF*4;
    const uint32_t sAl_u  = sAh_u + 2*ABUF*4;

    const int row = blockIdx.x;
    const int b = row / (DDISP*HH);
    const int d = (row / HH) % DDISP;
    const int h = row % HH;

    const int tid  = threadIdx.x;
    const int warp = tid >> 5;
    const int lane = tid & 31;
    const int g    = lane >> 2;
    const int p4   = lane & 3;
    const int m_base = warp * 16;
    const int HW = HH*WW;

    float acc[4][4];
#pragma unroll
    for (int nb = 0; nb < 4; nb++)
#pragma unroll
        for (int v = 0; v < 4; v++) acc[nb][v] = 0.f;

    // zero pad slots (aidx 3 and 132) in both buffers, both arrays
    if (tid < 4*2*NPAIR) {
        int e = tid;
        int buf  = e & 1;
        int arr  = (e >> 1) & 1;           // 0: hi, 1: lo
        int rsel = (e >> 2) & 1;           // 0: aidx3, 1: aidx132
        int p    = e >> 3;
        uint32_t* base = (arr ? sAl : sAh) + buf*ABUF;
        base[p*SA_STRIDE + (rsel ? 132 : 3)] = 0;
    }

    // valid tap list
    int tdd[9], thh[9], ttk[9]; int tcnt = 0;
    for (int kd = 0; kd < 3; kd++) {
        int dd = d + kd - 1; if (dd < 0 || dd >= DDISP) continue;
        for (int kh = 0; kh < 3; kh++) {
            int h2 = h + kh - 1; if (h2 < 0 || h2 >= HH) continue;
            tdd[tcnt] = dd; thh[tcnt] = h2; ttk[tcnt] = (kd*3 + kh)*3; tcnt++;
        }
    }

    auto ISSUE = [&](int t, int buf) {
        const int dd = tdd[t], h2 = thh[t];
        // A: hi+lo rows, 16B chunks
#pragma unroll
        for (int k = 0; k < (NPAIR*32)/256; k++) {
            int i = tid + k*256;
            const int p  = i >> 5;
            const int w4 = (i & 31) * 4;
            const uint32_t* srcH = &ph[((size_t)(b*NPAIR + p)*DDISP + dd)*HW + h2*WW + w4];
            const uint32_t* srcL = &pl[((size_t)(b*NPAIR + p)*DDISP + dd)*HW + h2*WW + w4];
            uint32_t off = (uint32_t)(buf*ABUF + p*SA_STRIDE + 4 + w4) * 4;
            CP_ASYNC16(sAh_u + off, srcH);
            CP_ASYNC16(sAl_u + off, srcL);
        }
        // B: contiguous tap-group block, 16B chunks
        {
            const uint32_t* srcB = wp + (size_t)ttk[t]*(NCH*8*32);
#pragma unroll
            for (int k = 0; k < (NB4 + 255)/256; k++) {
                int q = tid + k*256;
                if (q < NB4) {
                    int n4 = q & 7;
                    int r  = q >> 3;                    // ((kw*NCH+cc)*8+j)
                    uint32_t off = (uint32_t)(buf*SWBUF + r*SW_STRIDE + n4*4) * 4;
                    CP_ASYNC16(sW_u + off, srcB + q*4);
                }
            }
        }
    };

    auto COMPUTE = [&](int buf) {
        const uint32_t* sWb  = sW  + buf*SWBUF;
        const uint32_t* sAhb = sAh + buf*ABUF;
        const uint32_t* sAlb = sAl + buf*ABUF;
#pragma unroll 1
        for (int kw = 0; kw < 3; kw++) {
#pragma unroll 1
            for (int c = 0; c < NCH; c++) {
                const int bp  = c*8;
                const int col = m_base + g + kw + 3;
                uint32_t ah[4], al[4];
                ah[0] = sAhb[(bp + p4    )*SA_STRIDE + col];
                ah[1] = sAhb[(bp + p4    )*SA_STRIDE + col + 8];
                ah[2] = sAhb[(bp + p4 + 4)*SA_STRIDE + col];
                ah[3] = sAhb[(bp + p4 + 4)*SA_STRIDE + col + 8];
                al[0] = sAlb[(bp + p4    )*SA_STRIDE + col];
                al[1] = sAlb[(bp + p4    )*SA_STRIDE + col + 8];
                al[2] = sAlb[(bp + p4 + 4)*SA_STRIDE + col];
                al[3] = sAlb[(bp + p4 + 4)*SA_STRIDE + col + 8];

                const uint32_t* wb = sWb + (kw*NCH + c)*8*SW_STRIDE;
                uint4 bh0 = *(const uint4*)(wb + p4*SW_STRIDE + g*4);
                uint4 bh1 = *(const uint4*)(wb + (p4 + 4)*SW_STRIDE + g*4);

                mma16816(acc[0], ah, bh0.x, bh1.x);
                mma16816(acc[0], al, bh0.x, bh1.x);
                mma16816(acc[1], ah, bh0.y, bh1.y);
                mma16816(acc[1], al, bh0.y, bh1.y);
                mma16816(acc[2], ah, bh0.z, bh1.z);
                mma16816(acc[2], al, bh0.z, bh1.z);
                mma16816(acc[3], ah, bh0.w, bh1.w);
                mma16816(acc[3], al, bh0.w, bh1.w);
            }
        }
    };

    // ---- software pipeline over taps
    ISSUE(0, 0);
    CP_COMMIT();
#pragma unroll 1
    for (int t = 0; t < tcnt; t++) {
        if (t + 1 < tcnt) {
            ISSUE(t + 1, (t + 1) & 1);
            CP_COMMIT();
            CP_WAIT1();          // tap t landed; t+1 still in flight
        } else {
            CP_WAIT0();
        }
        __syncthreads();         // all threads see buffer t
        COMPUTE(t & 1);
        __syncthreads();         // buffer t free before next issue overwrites it
    }

    // ---- epilogue: smem transpose -> coalesced stores + fused BN partial sums
#pragma unroll
    for (int nb = 0; nb < 4; nb++) {
        const int co = nb*8 + 2*p4;
        sD[(co    )*SD_STRIDE + m_base + g    ] = acc[nb][0];
        sD[(co + 1)*SD_STRIDE + m_base + g    ] = acc[nb][1];
        sD[(co    )*SD_STRIDE + m_base + g + 8] = acc[nb][2];
        sD[(co + 1)*SD_STRIDE + m_base + g + 8] = acc[nb][3];
    }
    __syncthreads();
    for (int i = tid; i < HID*32; i += 256) {
        const int co = i >> 5;
        const int q  = (i & 31) * 4;
        float4 v = *(const float4*)&sD[co*SD_STRIDE + q];
        *(float4*)&out[(((size_t)b*HID + co)*DDISP + d)*(HH*WW) + h*WW + q] = v;
    }
    {
        const int co = tid >> 3;
        const int sg = tid & 7;
        const float* rp = &sD[co*SD_STRIDE + sg*16];
        float s = 0.f, sq = 0.f;
#pragma unroll
        for (int j = 0; j < 16; j++) { float v = rp[j]; s += v; sq += v*v; }
        sSum[co*8 + sg] = s;
        sSq [co*8 + sg] = sq;
    }
    __syncthreads();
    if (tid < HID) {
        float S = 0.f, Q = 0.f;
#pragma unroll
        for (int k = 0; k < 8; k++) { S += sSum[tid*8 + k]; Q += sSq[tid*8 + k]; }
        g_rsum[(size_t)tid*NROWS + row] = S;
        g_rsq [(size_t)tid*NROWS + row] = Q;
    }
}

// ---------------- BN finalize ----------------
__global__ __launch_bounds__(256)
void finalize2_kernel(const float* __restrict__ gamma,
                      const float* __restrict__ beta)
{
    const int ch = blockIdx.x;
    float s = 0.f, sq = 0.f;
    for (int r = threadIdx.x; r < NROWS; r += 256) {
        s  += g_rsum[(size_t)ch*NROWS + r];
        sq += g_rsq [(size_t)ch*NROWS + r];
    }
    __shared__ float rs[256], rq[256];
    rs[threadIdx.x] = s; rq[threadIdx.x] = sq;
    __syncthreads();
    for (int st = 128; st > 0; st >>= 1) {
        if (threadIdx.x < st) {
            rs[threadIdx.x] += rs[threadIdx.x + st];
            rq[threadIdx.x] += rq[threadIdx.x + st];
        }
        __syncthreads();
    }
    if (threadIdx.x == 0) {
        const float N = (float)(BB*SPA);
        float mean = rs[0] / N;
        float var  = fmaxf(rq[0] / N - mean*mean, 0.f);
        float scale = gamma[ch] * rsqrtf(var + EPSBN);
        g_ss[ch] = make_float2(scale, beta[ch] - mean*scale);
    }
}

// ---------------- final conv (32 -> 1), smem-tiled scalar ----------------
#define TD 2
#define TH 8
#define TW 16
#define CD 4
#define CH 10
#define CWD 18
#define CWP 19
#define CHUNK 4

__global__ __launch_bounds__(256)
void final_kernel(const float* __restrict__ x,
                  const float* __restrict__ wf,
                  const float* __restrict__ bf,
                  float* __restrict__ out)
{
    __shared__ float sIn[CHUNK][CD][CH][CWP];
    __shared__ float sw[HID*27];
    __shared__ float2 sss[HID];

    const int w0 = blockIdx.x * TW;
    const int h0 = blockIdx.y * TH;
    const int bz = blockIdx.z;
    const int b  = bz / (DDISP/TD);
    const int d0 = (bz % (DDISP/TD)) * TD;
    const int tid = threadIdx.x;

    const int tdz = tid >> 7;
    const int thy = (tid >> 4) & 7;
    const int twx = tid & 15;

    for (int i = tid; i < HID*27; i += 256) sw[i] = wf[i];
    if (tid < HID) sss[tid] = g_ss[tid];
    __syncthreads();

    float acc = 0.f;
    for (int c0 = 0; c0 < HID; c0 += CHUNK) {
        __syncthreads();
        for (int i = tid; i < CHUNK*CD*CH*CWD; i += 256) {
            int c  = i / (CD*CH*CWD);
            int r  = i % (CD*CH*CWD);
            int dz = r / (CH*CWD);
            int r2 = r % (CH*CWD);
            int hy = r2 / CWD;
            int wx = r2 % CWD;
            int gd = d0 - 1 + dz;
            int gh = h0 - 1 + hy;
            int gw = w0 - 1 + wx;
            float val = 0.f;
            if (gd >= 0 && gd < DDISP && gh >= 0 && gh < HH && gw >= 0 && gw < WW) {
                val = x[(((size_t)b*HID + (c0 + c))*DDISP + gd)*(HH*WW) + gh*WW + gw];
                float2 s = sss[c0 + c];
                val = fmaf(s.x, val, s.y);
                val = (val > 0.f) ? val : NEG*val;
            }
            sIn[c][dz][hy][wx] = val;
        }
        __syncthreads();

#pragma unroll 1
        for (int c = 0; c < CHUNK; c++) {
#pragma unroll
            for (int kd = 0; kd < 3; kd++) {
#pragma unroll
                for (int kh = 0; kh < 3; kh++) {
#pragma unroll
                    for (int kw = 0; kw < 3; kw++) {
                        acc = fmaf(sw[(c0 + c)*27 + (kd*3 + kh)*3 + kw],
                                   sIn[c][tdz + kd][thy + kh][twx + kw], acc);
                    }
                }
            }
        }
    }

    const int gd = d0 + tdz, gh = h0 + thy, gw = w0 + twx;
    out[(((size_t)b*DDISP + gd)*HH + gh)*WW + gw] = acc + bf[0];
}

// ---------------- launch ----------------
extern "C" void kernel_launch(void* const* d_in, const int* in_sizes, int n_in,
                              void* d_out, int out_size)
{
    const float* left  = (const float*)d_in[0];
    const float* right = (const float*)d_in[1];
    const float* w1 = (const float*)d_in[2];
    const float* g1 = (const float*)d_in[3];
    const float* b1 = (const float*)d_in[4];
    const float* w2 = (const float*)d_in[5];
    const float* g2 = (const float*)d_in[6];
    const float* b2 = (const float*)d_in[7];
    const float* w3 = (const float*)d_in[8];
    const float* g3 = (const float*)d_in[9];
    const float* b3 = (const float*)d_in[10];
    const float* w4 = (const float*)d_in[11];
    const float* g4 = (const float*)d_in[12];
    const float* b4 = (const float*)d_in[13];
    const float* wf = (const float*)d_in[14];
    const float* bf = (const float*)d_in[15];
    float* out = (float*)d_out;
    (void)in_sizes; (void)n_in; (void)out_size;

    float *buf;
    uint32_t *wp, *phb, *plb;
    cudaGetSymbolAddress((void**)&buf, g_buf0);
    cudaGetSymbolAddress((void**)&wp,  g_wp);
    cudaGetSymbolAddress((void**)&phb, g_ph);
    cudaGetSymbolAddress((void**)&plb, g_pl);
    uint32_t* ph0 = phb;        uint32_t* pl0 = plb;
    uint32_t* ph1 = phb + PKE;  uint32_t* pl1 = plb + PKE;

    // dynamic smem sizes (bytes): double-buffered pipeline vs epilogue overlay
    const int SD_BYTES = (HID*SD_STRIDE + 512)*4;
    const int SM16_raw = 2*(3*1*8*SW_STRIDE + 2*8*SA_STRIDE)*4;    // 25088
    const int SM32_raw = 2*(3*2*8*SW_STRIDE + 2*16*SA_STRIDE)*4;   // 50176
    const int SMEM16 = (SM16_raw > SD_BYTES) ? SM16_raw : SD_BYTES;
    const int SMEM32 = (SM32_raw > SD_BYTES) ? SM32_raw : SD_BYTES;

    cudaFuncSetAttribute(conv_mma<16>, cudaFuncAttributeMaxDynamicSharedMemorySize, SMEM16);
    cudaFuncSetAttribute(conv_mma<32>, cudaFuncAttributeMaxDynamicSharedMemorySize, SMEM32);

    dim3 cgrid(WW/TW, HH/TH, BB*(DDISP/TD));
    const int SPLIT_GRID = PKE/256;

    wpack_kernel<<<27, 256>>>(w1, 16, wp + 0*WP_LAYER_U32);
    wpack_kernel<<<27, 256>>>(w2, 32, wp + 1*WP_LAYER_U32);
    wpack_kernel<<<27, 256>>>(w3, 32, wp + 2*WP_LAYER_U32);
    wpack_kernel<<<27, 256>>>(w4, 32, wp + 3*WP_LAYER_U32);

    vol_pack_kernel<<<BB*8*HH, 128>>>(left, right, ph0, pl0);

    conv_mma<16><<<NROWS, 256, SMEM16>>>(ph0, pl0, wp + 0*WP_LAYER_U32, buf);
    finalize2_kernel<<<HID, 256>>>(g1, b1);
    split_kernel<<<SPLIT_GRID, 256>>>(buf, ph1, pl1);

    conv_mma<32><<<NROWS, 256, SMEM32>>>(ph1, pl1, wp + 1*WP_LAYER_U32, buf);
    finalize2_kernel<<<HID, 256>>>(g2, b2);
    split_kernel<<<SPLIT_GRID, 256>>>(buf, ph0, pl0);

    conv_mma<32><<<NROWS, 256, SMEM32>>>(ph0, pl0, wp + 2*WP_LAYER_U32, buf);
    finalize2_kernel<<<HID, 256>>>(g3, b3);
    split_kernel<<<SPLIT_GRID, 256>>>(buf, ph1, pl1);

    conv_mma<32><<<NROWS, 256, SMEM32>>>(ph1, pl1, wp + 3*WP_LAYER_U32, buf);
    finalize2_kernel<<<HID, 256>>>(g4, b4);

    final_kernel<<<cgrid, 256>>>(buf, wf, bf, out);
}

// round 17
// speedup vs baseline: 1.6796x; 1.0610x over previous
#include <cuda_runtime.h>
#include <cuda_fp16.h>
#include <cstdint>

// ---------------- problem constants ----------------
#define BB    2
#define CFEAT 128
#define HH    64
#define WW    128
#define GG    16
#define CPG   8
#define DDISP 48
#define HID   32
#define NEG   0.2f
#define EPSBN 1e-5f

#define SPA    (DDISP*HH*WW)
#define X_ELEMS (BB*HID*SPA)
#define NROWS  (BB*DDISP*HH)          // 6144
#define PKE    (BB*16*SPA)

// ---------------- scratch ----------------
__device__ float    g_buf0[X_ELEMS];
__device__ uint32_t g_ph[2*PKE];              // fp16 hi pairs
__device__ uint32_t g_pl[2*PKE];              // fp16 lo (residual) pairs
__device__ float    g_rsum[HID*NROWS];
__device__ float    g_rsq [HID*NROWS];
__device__ float2   g_ss  [HID];
__device__ unsigned int g_ctr[4];             // per-conv-layer row counters
// packed fp16 weight fragments: [tap 27][chunk NCH][j 8][n' 32], n' = (n&7)*4 + (n>>3)
#define WP_LAYER_U32 (27*2*8*32)
__device__ uint32_t g_wp[4*WP_LAYER_U32];

// ---------------- mma.sync / cp.async helpers ----------------
__device__ __forceinline__ void mma16816(float d[4], const uint32_t a[4],
                                         uint32_t b0, uint32_t b1)
{
    asm volatile(
        "mma.sync.aligned.m16n8k16.row.col.f32.f16.f16.f32 "
        "{%0,%1,%2,%3}, {%4,%5,%6,%7}, {%8,%9}, {%0,%1,%2,%3};\n"
        : "+f"(d[0]), "+f"(d[1]), "+f"(d[2]), "+f"(d[3])
        : "r"(a[0]), "r"(a[1]), "r"(a[2]), "r"(a[3]), "r"(b0), "r"(b1));
}
#define CP_ASYNC16(dst_smem_u32addr, src_gptr) \
    asm volatile("cp.async.cg.shared.global [%0], [%1], 16;" \
                 :: "r"(dst_smem_u32addr), "l"(src_gptr) : "memory")
#define CP_COMMIT() asm volatile("cp.async.commit_group;" ::: "memory")
#define CP_WAIT0()  asm volatile("cp.async.wait_group 0;" ::: "memory")
#define CP_WAIT1()  asm volatile("cp.async.wait_group 1;" ::: "memory")

__device__ __forceinline__ uint32_t pack_f16x2(__half lo, __half hi)
{
    unsigned short u0 = *reinterpret_cast<unsigned short*>(&lo);
    unsigned short u1 = *reinterpret_cast<unsigned short*>(&hi);
    return (uint32_t)u0 | ((uint32_t)u1 << 16);
}

__device__ __forceinline__ void split_pack(float v0, float v1,
                                           uint32_t& hi, uint32_t& lo)
{
    __half h0 = __float2half_rn(v0);
    __half h1 = __float2half_rn(v1);
    __half l0 = __float2half_rn(v0 - __half2float(h0));
    __half l1 = __float2half_rn(v1 - __half2float(h1));
    hi = pack_f16x2(h0, h1);
    lo = pack_f16x2(l0, l1);
}

// ---------------- volume build, emitting packed hi/lo directly ----------------
__global__ void vol_pack_kernel(const float* __restrict__ left,
                                const float* __restrict__ right,
                                uint32_t* __restrict__ ph,
                                uint32_t* __restrict__ pl)
{
    if (blockIdx.x == 0 && threadIdx.x == 0) {
        g_ctr[0] = 0; g_ctr[1] = 0; g_ctr[2] = 0; g_ctr[3] = 0;
    }

    int h = blockIdx.x % HH;
    int p = (blockIdx.x / HH) % 8;
    int b = blockIdx.x / (HH*8);
    int w = threadIdx.x;                       // 128

    __shared__ float sR[16][WW];
    float l[16];
    const float* lp = left  + (((size_t)b*CFEAT + p*16)*HH + h)*WW + w;
    const float* rp = right + (((size_t)b*CFEAT + p*16)*HH + h)*WW + w;
#pragma unroll
    for (int c = 0; c < 16; c++) {
        l[c]     = lp[(size_t)c*HH*WW];
        sR[c][w] = rp[(size_t)c*HH*WW];
    }
    __syncthreads();

    uint32_t* hp  = ph + ((size_t)(b*8 + p)*DDISP)*(HH*WW) + h*WW + w;
    uint32_t* lp2 = pl + ((size_t)(b*8 + p)*DDISP)*(HH*WW) + h*WW + w;
    for (int d = 0; d < DDISP; d++) {
        float s0 = 0.f, s1 = 0.f;
        if (w >= d) {
            int ws = w - d;
#pragma unroll
            for (int c = 0; c < 8; c++)  s0 += l[c]*sR[c][ws];
#pragma unroll
            for (int c = 8; c < 16; c++) s1 += l[c]*sR[c][ws];
        }
        s0 *= (1.0f/CPG); s1 *= (1.0f/CPG);
        uint32_t hi, lo;
        split_pack(s0, s1, hi, lo);
        hp [(size_t)d*HH*WW] = hi;
        lp2[(size_t)d*HH*WW] = lo;
    }
}

// ---------------- weight fragment pre-pack (fp16, n-permuted) ----------------
__global__ void wpack_kernel(const float* __restrict__ wg, int cin,
                             uint32_t* __restrict__ dst)
{
    const int t = blockIdx.x;            // 0..26
    const int nch = cin / 16;
    const int elems = nch * 256;
    for (int i = threadIdx.x; i < elems; i += 256) {
        int n  = i & 31;
        int j  = (i >> 5) & 7;
        int c  = i >> 8;
        int ci0 = c*16 + 2*j;
        float w0 = wg[((size_t)n*cin + ci0    )*27 + t];
        float w1 = wg[((size_t)n*cin + ci0 + 1)*27 + t];
        __half p0 = __float2half_rn(w0);
        __half p1 = __float2half_rn(w1);
        int nprime = (n & 7)*4 + (n >> 3);
        dst[(((size_t)t*nch + c)*8 + j)*32 + nprime] = pack_f16x2(p0, p1);
    }
}

// ---------------- BN split pass ----------------
__global__ __launch_bounds__(256)
void split_kernel(const float* __restrict__ y,
                  uint32_t* __restrict__ ph, uint32_t* __restrict__ pl)
{
    int idx = blockIdx.x * 256 + threadIdx.x;
    int r = idx % SPA;
    int p = (idx / SPA) % 16;
    int b = idx / (16*SPA);

    float v0 = y[((size_t)b*HID + 2*p    )*SPA + r];
    float v1 = y[((size_t)b*HID + 2*p + 1)*SPA + r];
    float2 s0 = g_ss[2*p], s1 = g_ss[2*p + 1];
    v0 = fmaf(s0.x, v0, s0.y); v0 = (v0 > 0.f) ? v0 : NEG*v0;
    v1 = fmaf(s1.x, v1, s1.y); v1 = (v1 > 0.f) ? v1 : NEG*v1;
    uint32_t hi, lo;
    split_pack(v0, v1, hi, lo);
    ph[idx] = hi;
    pl[idx] = lo;
}

// ---------------- cp.async double-buffered implicit-GEMM conv3d (persistent) ----------------
#define SA_STRIDE 136      // u32 per ci-pair row; data at +4, pads at 3 and 132
#define SW_STRIDE 40
#define SD_STRIDE 132

template<int CIN>
__global__ __launch_bounds__(256)
void conv_mma(const uint32_t* __restrict__ ph,
              const uint32_t* __restrict__ pl,
              const uint32_t* __restrict__ wp,
              float* __restrict__ out,
              int lidx)
{
    constexpr int NCH   = CIN / 16;
    constexpr int NPAIR = CIN / 2;
    constexpr int SWBUF = 3*NCH*8*SW_STRIDE;       // u32 per B buffer
    constexpr int ABUF  = NPAIR*SA_STRIDE;         // u32 per A array buffer
    constexpr int NB4   = 3*NCH*8*8;               // B uint4 per tap group

    extern __shared__ __align__(16) uint8_t smem[];
    uint32_t* sW  = (uint32_t*)smem;               // [2][SWBUF]
    uint32_t* sAh = sW + 2*SWBUF;                  // [2][ABUF]
    uint32_t* sAl = sAh + 2*ABUF;                  // [2][ABUF]
    float*    sD  = (float*)smem;                  // epilogue overlay
    float*    sSum = sD + HID*SD_STRIDE;
    float*    sSq  = sSum + 256;
    __shared__ unsigned int s_row;

    const uint32_t smem_u = (uint32_t)__cvta_generic_to_shared(smem);
    const uint32_t sW_u   = smem_u;
    const uint32_t sAh_u  = smem_u + 2*SWBUF*4;
    const uint32_t sAl_u  = sAh_u + 2*ABUF*4;

    const int tid  = threadIdx.x;
    const int warp = tid >> 5;
    const int lane = tid & 31;
    const int g    = lane >> 2;
    const int p4   = lane & 3;
    const int m_base = warp * 16;
    const int HW = HH*WW;

    for (;;) {
        if (tid == 0) s_row = atomicAdd(&g_ctr[lidx], 1u);
        __syncthreads();                       // broadcast row; also orders prior row's
        const unsigned int row = s_row;        // sSum reads before new pad writes
        if (row >= NROWS) break;

        const int b = row / (DDISP*HH);
        const int d = (row / HH) % DDISP;
        const int h = row % HH;

        float acc[4][4];
#pragma unroll
        for (int nb = 0; nb < 4; nb++)
#pragma unroll
            for (int v = 0; v < 4; v++) acc[nb][v] = 0.f;

        // zero pad slots (aidx 3 and 132) in both buffers, both arrays
        if (tid < 4*2*NPAIR) {
            int e = tid;
            int buf  = e & 1;
            int arr  = (e >> 1) & 1;
            int rsel = (e >> 2) & 1;
            int p    = e >> 3;
            uint32_t* base = (arr ? sAl : sAh) + buf*ABUF;
            base[p*SA_STRIDE + (rsel ? 132 : 3)] = 0;
        }

        // valid tap list
        int tdd[9], thh[9], ttk[9]; int tcnt = 0;
        for (int kd = 0; kd < 3; kd++) {
            int dd = d + kd - 1; if (dd < 0 || dd >= DDISP) continue;
            for (int kh = 0; kh < 3; kh++) {
                int h2 = h + kh - 1; if (h2 < 0 || h2 >= HH) continue;
                tdd[tcnt] = dd; thh[tcnt] = h2; ttk[tcnt] = (kd*3 + kh)*3; tcnt++;
            }
        }

        auto ISSUE = [&](int t, int buf) {
            const int dd = tdd[t], h2 = thh[t];
#pragma unroll
            for (int k = 0; k < (NPAIR*32)/256; k++) {
                int i = tid + k*256;
                const int p  = i >> 5;
                const int w4 = (i & 31) * 4;
                const uint32_t* srcH = &ph[((size_t)(b*NPAIR + p)*DDISP + dd)*HW + h2*WW + w4];
                const uint32_t* srcL = &pl[((size_t)(b*NPAIR + p)*DDISP + dd)*HW + h2*WW + w4];
                uint32_t off = (uint32_t)(buf*ABUF + p*SA_STRIDE + 4 + w4) * 4;
                CP_ASYNC16(sAh_u + off, srcH);
                CP_ASYNC16(sAl_u + off, srcL);
            }
            {
                const uint32_t* srcB = wp + (size_t)ttk[t]*(NCH*8*32);
#pragma unroll
                for (int k = 0; k < (NB4 + 255)/256; k++) {
                    int q = tid + k*256;
                    if (q < NB4) {
                        int n4 = q & 7;
                        int r  = q >> 3;
                        uint32_t off = (uint32_t)(buf*SWBUF + r*SW_STRIDE + n4*4) * 4;
                        CP_ASYNC16(sW_u + off, srcB + q*4);
                    }
                }
            }
        };

        auto COMPUTE = [&](int buf) {
            const uint32_t* sWb  = sW  + buf*SWBUF;
            const uint32_t* sAhb = sAh + buf*ABUF;
            const uint32_t* sAlb = sAl + buf*ABUF;
#pragma unroll 1
            for (int kw = 0; kw < 3; kw++) {
#pragma unroll 1
                for (int c = 0; c < NCH; c++) {
                    const int bp  = c*8;
                    const int col = m_base + g + kw + 3;
                    uint32_t ah[4], al[4];
                    ah[0] = sAhb[(bp + p4    )*SA_STRIDE + col];
                    ah[1] = sAhb[(bp + p4    )*SA_STRIDE + col + 8];
                    ah[2] = sAhb[(bp + p4 + 4)*SA_STRIDE + col];
                    ah[3] = sAhb[(bp + p4 + 4)*SA_STRIDE + col + 8];
                    al[0] = sAlb[(bp + p4    )*SA_STRIDE + col];
                    al[1] = sAlb[(bp + p4    )*SA_STRIDE + col + 8];
                    al[2] = sAlb[(bp + p4 + 4)*SA_STRIDE + col];
                    al[3] = sAlb[(bp + p4 + 4)*SA_STRIDE + col + 8];

                    const uint32_t* wb = sWb + (kw*NCH + c)*8*SW_STRIDE;
                    uint4 bh0 = *(const uint4*)(wb + p4*SW_STRIDE + g*4);
                    uint4 bh1 = *(const uint4*)(wb + (p4 + 4)*SW_STRIDE + g*4);

                    mma16816(acc[0], ah, bh0.x, bh1.x);
                    mma16816(acc[0], al, bh0.x, bh1.x);
                    mma16816(acc[1], ah, bh0.y, bh1.y);
                    mma16816(acc[1], al, bh0.y, bh1.y);
                    mma16816(acc[2], ah, bh0.z, bh1.z);
                    mma16816(acc[2], al, bh0.z, bh1.z);
                    mma16816(acc[3], ah, bh0.w, bh1.w);
                    mma16816(acc[3], al, bh0.w, bh1.w);
                }
            }
        };

        // ---- software pipeline over taps
        ISSUE(0, 0);
        CP_COMMIT();
#pragma unroll 1
        for (int t = 0; t < tcnt; t++) {
            if (t + 1 < tcnt) {
                ISSUE(t + 1, (t + 1) & 1);
                CP_COMMIT();
                CP_WAIT1();
            } else {
                CP_WAIT0();
            }
            __syncthreads();
            COMPUTE(t & 1);
            __syncthreads();
        }

        // ---- epilogue: smem transpose -> coalesced stores + fused BN partial sums
#pragma unroll
        for (int nb = 0; nb < 4; nb++) {
            const int co = nb*8 + 2*p4;
            sD[(co    )*SD_STRIDE + m_base + g    ] = acc[nb][0];
            sD[(co + 1)*SD_STRIDE + m_base + g    ] = acc[nb][1];
            sD[(co    )*SD_STRIDE + m_base + g + 8] = acc[nb][2];
            sD[(co + 1)*SD_STRIDE + m_base + g + 8] = acc[nb][3];
        }
        __syncthreads();
        for (int i = tid; i < HID*32; i += 256) {
            const int co = i >> 5;
            const int q  = (i & 31) * 4;
            float4 v = *(const float4*)&sD[co*SD_STRIDE + q];
            *(float4*)&out[(((size_t)b*HID + co)*DDISP + d)*(HH*WW) + h*WW + q] = v;
        }
        {
            const int co = tid >> 3;
            const int sg = tid & 7;
            const float* rp = &sD[co*SD_STRIDE + sg*16];
            float s = 0.f, sq = 0.f;
#pragma unroll
            for (int j = 0; j < 16; j++) { float v = rp[j]; s += v; sq += v*v; }
            sSum[co*8 + sg] = s;
            sSq [co*8 + sg] = sq;
        }
        __syncthreads();
        if (tid < HID) {
            float S = 0.f, Q = 0.f;
#pragma unroll
            for (int k = 0; k < 8; k++) { S += sSum[tid*8 + k]; Q += sSq[tid*8 + k]; }
            g_rsum[(size_t)tid*NROWS + row] = S;
            g_rsq [(size_t)tid*NROWS + row] = Q;
        }
    }
}

// ---------------- BN finalize ----------------
__global__ __launch_bounds__(256)
void finalize2_kernel(const float* __restrict__ gamma,
                      const float* __restrict__ beta)
{
    const int ch = blockIdx.x;
    float s = 0.f, sq = 0.f;
    for (int r = threadIdx.x; r < NROWS; r += 256) {
        s  += g_rsum[(size_t)ch*NROWS + r];
        sq += g_rsq [(size_t)ch*NROWS + r];
    }
    __shared__ float rs[256], rq[256];
    rs[threadIdx.x] = s; rq[threadIdx.x] = sq;
    __syncthreads();
    for (int st = 128; st > 0; st >>= 1) {
        if (threadIdx.x < st) {
            rs[threadIdx.x] += rs[threadIdx.x + st];
            rq[threadIdx.x] += rq[threadIdx.x + st];
        }
        __syncthreads();
    }
    if (threadIdx.x == 0) {
        const float N = (float)(BB*SPA);
        float mean = rs[0] / N;
        float var  = fmaxf(rq[0] / N - mean*mean, 0.f);
        float scale = gamma[ch] * rsqrtf(var + EPSBN);
        g_ss[ch] = make_float2(scale, beta[ch] - mean*scale);
    }
}

// ---------------- final conv (32 -> 1), smem-tiled scalar ----------------
#define TD 2
#define TH 8
#define TW 16
#define CD 4
#define CH 10
#define CWD 18
#define CWP 19
#define CHUNK 4

__global__ __launch_bounds__(256)
void final_kernel(const float* __restrict__ x,
                  const float* __restrict__ wf,
                  const float* __restrict__ bf,
                  float* __restrict__ out)
{
    __shared__ float sIn[CHUNK][CD][CH][CWP];
    __shared__ float sw[HID*27];
    __shared__ float2 sss[HID];

    const int w0 = blockIdx.x * TW;
    const int h0 = blockIdx.y * TH;
    const int bz = blockIdx.z;
    const int b  = bz / (DDISP/TD);
    const int d0 = (bz % (DDISP/TD)) * TD;
    const int tid = threadIdx.x;

    const int tdz = tid >> 7;
    const int thy = (tid >> 4) & 7;
    const int twx = tid & 15;

    for (int i = tid; i < HID*27; i += 256) sw[i] = wf[i];
    if (tid < HID) sss[tid] = g_ss[tid];
    __syncthreads();

    float acc = 0.f;
    for (int c0 = 0; c0 < HID; c0 += CHUNK) {
        __syncthreads();
        for (int i = tid; i < CHUNK*CD*CH*CWD; i += 256) {
            int c  = i / (CD*CH*CWD);
            int r  = i % (CD*CH*CWD);
            int dz = r / (CH*CWD);
            int r2 = r % (CH*CWD);
            int hy = r2 / CWD;
            int wx = r2 % CWD;
            int gd = d0 - 1 + dz;
            int gh = h0 - 1 + hy;
            int gw = w0 - 1 + wx;
            float val = 0.f;
            if (gd >= 0 && gd < DDISP && gh >= 0 && gh < HH && gw >= 0 && gw < WW) {
                val = x[(((size_t)b*HID + (c0 + c))*DDISP + gd)*(HH*WW) + gh*WW + gw];
                float2 s = sss[c0 + c];
                val = fmaf(s.x, val, s.y);
                val = (val > 0.f) ? val : NEG*val;
            }
            sIn[c][dz][hy][wx] = val;
        }
        __syncthreads();

#pragma unroll 1
        for (int c = 0; c < CHUNK; c++) {
#pragma unroll
            for (int kd = 0; kd < 3; kd++) {
#pragma unroll
                for (int kh = 0; kh < 3; kh++) {
#pragma unroll
                    for (int kw = 0; kw < 3; kw++) {
                        acc = fmaf(sw[(c0 + c)*27 + (kd*3 + kh)*3 + kw],
                                   sIn[c][tdz + kd][thy + kh][twx + kw], acc);
                    }
                }
            }
        }
    }

    const int gd = d0 + tdz, gh = h0 + thy, gw = w0 + twx;
    out[(((size_t)b*DDISP + gd)*HH + gh)*WW + gw] = acc + bf[0];
}

// ---------------- launch ----------------
extern "C" void kernel_launch(void* const* d_in, const int* in_sizes, int n_in,
                              void* d_out, int out_size)
{
    const float* left  = (const float*)d_in[0];
    const float* right = (const float*)d_in[1];
    const float* w1 = (const float*)d_in[2];
    const float* g1 = (const float*)d_in[3];
    const float* b1 = (const float*)d_in[4];
    const float* w2 = (const float*)d_in[5];
    const float* g2 = (const float*)d_in[6];
    const float* b2 = (const float*)d_in[7];
    const float* w3 = (const float*)d_in[8];
    const float* g3 = (const float*)d_in[9];
    const float* b3 = (const float*)d_in[10];
    const float* w4 = (const float*)d_in[11];
    const float* g4 = (const float*)d_in[12];
    const float* b4 = (const float*)d_in[13];
    const float* wf = (const float*)d_in[14];
    const float* bf = (const float*)d_in[15];
    float* out = (float*)d_out;
    (void)in_sizes; (void)n_in; (void)out_size;

    float *buf;
    uint32_t *wp, *phb, *plb;
    cudaGetSymbolAddress((void**)&buf, g_buf0);
    cudaGetSymbolAddress((void**)&wp,  g_wp);
    cudaGetSymbolAddress((void**)&phb, g_ph);
    cudaGetSymbolAddress((void**)&plb, g_pl);
    uint32_t* ph0 = phb;        uint32_t* pl0 = plb;
    uint32_t* ph1 = phb + PKE;  uint32_t* pl1 = plb + PKE;

    // dynamic smem sizes (bytes): double-buffered pipeline vs epilogue overlay
    const int SD_BYTES = (HID*SD_STRIDE + 512)*4;
    const int SM16_raw = 2*(3*1*8*SW_STRIDE + 2*8*SA_STRIDE)*4;    // 25088
    const int SM32_raw = 2*(3*2*8*SW_STRIDE + 2*16*SA_STRIDE)*4;   // 50176
    const int SMEM16 = (SM16_raw > SD_BYTES) ? SM16_raw : SD_BYTES;
    const int SMEM32 = (SM32_raw > SD_BYTES) ? SM32_raw : SD_BYTES;

    cudaFuncSetAttribute(conv_mma<16>, cudaFuncAttributeMaxDynamicSharedMemorySize, SMEM16);
    cudaFuncSetAttribute(conv_mma<32>, cudaFuncAttributeMaxDynamicSharedMemorySize, SMEM32);

    dim3 cgrid(WW/TW, HH/TH, BB*(DDISP/TD));
    const int SPLIT_GRID = PKE/256;

    wpack_kernel<<<27, 256>>>(w1, 16, wp + 0*WP_LAYER_U32);
    wpack_kernel<<<27, 256>>>(w2, 32, wp + 1*WP_LAYER_U32);
    wpack_kernel<<<27, 256>>>(w3, 32, wp + 2*WP_LAYER_U32);
    wpack_kernel<<<27, 256>>>(w4, 32, wp + 3*WP_LAYER_U32);

    vol_pack_kernel<<<BB*8*HH, 128>>>(left, right, ph0, pl0);   // also resets g_ctr[]

    conv_mma<16><<<NROWS, 256, SMEM16>>>(ph0, pl0, wp + 0*WP_LAYER_U32, buf, 0);
    finalize2_kernel<<<HID, 256>>>(g1, b1);
    split_kernel<<<SPLIT_GRID, 256>>>(buf, ph1, pl1);

    conv_mma<32><<<NROWS, 256, SMEM32>>>(ph1, pl1, wp + 1*WP_LAYER_U32, buf, 1);
    finalize2_kernel<<<HID, 256>>>(g2, b2);
    split_kernel<<<SPLIT_GRID, 256>>>(buf, ph0, pl0);

    conv_mma<32><<<NROWS, 256, SMEM32>>>(ph0, pl0, wp + 2*WP_LAYER_U32, buf, 2);
    finalize2_kernel<<<HID, 256>>>(g3, b3);
    split_kernel<<<SPLIT_GRID, 256>>>(buf, ph1, pl1);

    conv_mma<32><<<NROWS, 256, SMEM32>>>(ph1, pl1, wp + 3*WP_LAYER_U32, buf, 3);
    finalize2_kernel<<<HID, 256>>>(g4, b4);

    final_kernel<<<cgrid, 256>>>(buf, wf, bf, out);
}